// round 1
// baseline (speedup 1.0000x reference)
#include <cuda_runtime.h>
#include <math.h>

#define BB 4
#define SS 1024
#define DD 1024
#define HH 16
#define HDIM 64
#define FF 4096
#define LL 6
#define MM (BB*SS)          // 4096 rows
#define EPSV 1e-5f

// ---------------- scratch (device globals; no allocation allowed) ----------------
__device__ float g_x[MM*DD];                    // activations [4096,1024]
__device__ float g_y[MM*DD];                    // attn_out / ffn_out
__device__ float g_vals[MM*DD];                 // attention values (re-assembled heads)
__device__ float g_qkv[MM*3*DD];                // [4096, 3072]
__device__ float g_ff[MM*FF];                   // [4096, 4096]
__device__ float g_scores[(size_t)BB*HH*SS*SS]; // [64, 1024, 1024] = 256 MB

// ---------------- reductions ----------------
__device__ __forceinline__ float warpReduceSum(float v) {
    #pragma unroll
    for (int o = 16; o; o >>= 1) v += __shfl_xor_sync(0xffffffffu, v, o);
    return v;
}
__device__ __forceinline__ float warpReduceMax(float v) {
    #pragma unroll
    for (int o = 16; o; o >>= 1) v = fmaxf(v, __shfl_xor_sync(0xffffffffu, v, o));
    return v;
}
// blockDim.x == 256 assumed
__device__ __forceinline__ float blockReduceSum(float v, float* sh) {
    v = warpReduceSum(v);
    int w = threadIdx.x >> 5;
    __syncthreads();
    if ((threadIdx.x & 31) == 0) sh[w] = v;
    __syncthreads();
    if (threadIdx.x < 32) {
        float t = (threadIdx.x < 8) ? sh[threadIdx.x] : 0.f;
        t = warpReduceSum(t);
        if (threadIdx.x == 0) sh[0] = t;
    }
    __syncthreads();
    return sh[0];
}
__device__ __forceinline__ float blockReduceMax(float v, float* sh) {
    v = warpReduceMax(v);
    int w = threadIdx.x >> 5;
    __syncthreads();
    if ((threadIdx.x & 31) == 0) sh[w] = v;
    __syncthreads();
    if (threadIdx.x < 32) {
        float t = (threadIdx.x < 8) ? sh[threadIdx.x] : -INFINITY;
        t = warpReduceMax(t);
        if (threadIdx.x == 0) sh[0] = t;
    }
    __syncthreads();
    return sh[0];
}

// ---------------- embedding + interleaved sinusoidal PE ----------------
__global__ __launch_bounds__(256) void embed_kernel(const int* __restrict__ tokens,
                                                    const float* __restrict__ emb,
                                                    float* __restrict__ x) {
    int row = blockIdx.x;           // b*S + s
    int s = row & (SS - 1);
    int tok = tokens[row];
    const float* e = emb + (size_t)tok * DD;
    float* xr = x + (size_t)row * DD;
    for (int d = threadIdx.x; d < DD; d += 256) {
        int i2 = d & ~1;
        float denom = powf(10000.0f, (float)i2 / (float)DD);
        float ang = (float)s / denom;
        float pe = (d & 1) ? cosf(ang) : sinf(ang);
        xr[d] = e[d] + pe;
    }
}

// ---------------- generic SGEMM: C[M,N] = A[M,K] @ B[K,N] + bias, opt. ReLU ----------
// grid: (N/128, M/128), block: 256. lda/ldb/ldc in elements.
template<int RELU>
__global__ __launch_bounds__(256) void gemm_nn(const float* __restrict__ A, int lda,
                                               const float* __restrict__ B, int ldb,
                                               const float* __restrict__ bias,
                                               float* __restrict__ C, int ldc,
                                               int K) {
    __shared__ float As[16][132];
    __shared__ float Bs[16][128];
    int tid = threadIdx.x;
    int bm = blockIdx.y * 128, bn = blockIdx.x * 128;
    int tx = tid & 15, ty = tid >> 4;
    int arow = tid >> 2, acol = (tid & 3) << 2;     // A: 64 rows x 4 float4 per pass (x2)
    int brow = tid >> 5, bcol = (tid & 31) << 2;    // B: 8 rows x 32 float4 per pass (x2)
    float acc[8][8];
    #pragma unroll
    for (int i = 0; i < 8; i++)
        #pragma unroll
        for (int j = 0; j < 8; j++) acc[i][j] = 0.f;

    for (int k0 = 0; k0 < K; k0 += 16) {
        float4 a0 = *(const float4*)(A + (size_t)(bm + arow) * lda + k0 + acol);
        float4 a1 = *(const float4*)(A + (size_t)(bm + arow + 64) * lda + k0 + acol);
        float4 b0 = *(const float4*)(B + (size_t)(k0 + brow) * ldb + bn + bcol);
        float4 b1 = *(const float4*)(B + (size_t)(k0 + brow + 8) * ldb + bn + bcol);
        __syncthreads();
        As[acol + 0][arow] = a0.x; As[acol + 1][arow] = a0.y;
        As[acol + 2][arow] = a0.z; As[acol + 3][arow] = a0.w;
        As[acol + 0][arow + 64] = a1.x; As[acol + 1][arow + 64] = a1.y;
        As[acol + 2][arow + 64] = a1.z; As[acol + 3][arow + 64] = a1.w;
        *(float4*)&Bs[brow][bcol]     = b0;
        *(float4*)&Bs[brow + 8][bcol] = b1;
        __syncthreads();
        #pragma unroll
        for (int k = 0; k < 16; k++) {
            float ra[8], rb[8];
            #pragma unroll
            for (int i = 0; i < 8; i++) ra[i] = As[k][ty * 8 + i];
            #pragma unroll
            for (int j = 0; j < 8; j++) rb[j] = Bs[k][tx * 8 + j];
            #pragma unroll
            for (int i = 0; i < 8; i++)
                #pragma unroll
                for (int j = 0; j < 8; j++) acc[i][j] = fmaf(ra[i], rb[j], acc[i][j]);
        }
    }
    #pragma unroll
    for (int i = 0; i < 8; i++) {
        float* crow = C + (size_t)(bm + ty * 8 + i) * ldc + bn + tx * 8;
        #pragma unroll
        for (int j4 = 0; j4 < 2; j4++) {
            float4 v;
            float b0v = bias[bn + tx * 8 + j4 * 4 + 0];
            float b1v = bias[bn + tx * 8 + j4 * 4 + 1];
            float b2v = bias[bn + tx * 8 + j4 * 4 + 2];
            float b3v = bias[bn + tx * 8 + j4 * 4 + 3];
            v.x = acc[i][j4 * 4 + 0] + b0v;
            v.y = acc[i][j4 * 4 + 1] + b1v;
            v.z = acc[i][j4 * 4 + 2] + b2v;
            v.w = acc[i][j4 * 4 + 3] + b3v;
            if (RELU) {
                v.x = fmaxf(v.x, 0.f); v.y = fmaxf(v.y, 0.f);
                v.z = fmaxf(v.z, 0.f); v.w = fmaxf(v.w, 0.f);
            }
            *(float4*)(crow + j4 * 4) = v;
        }
    }
}

// ---------------- scores = q @ k^T per (b,h); raw (scale applied in softmax) --------
// grid: (8, 8, 64) = (t-tiles, s-tiles, B*H), block 256
__global__ __launch_bounds__(256) void scores_gemm(const float* __restrict__ qkv,
                                                   float* __restrict__ scores) {
    __shared__ float Qs[16][132];
    __shared__ float Ks[16][132];
    int bh = blockIdx.z;
    int b = bh >> 4, h = bh & 15;
    const float* qb = qkv + (size_t)b * SS * (3 * DD) + h * (3 * HDIM);
    const float* kb = qb + HDIM;
    int tid = threadIdx.x;
    int tx = tid & 15, ty = tid >> 4;
    int arow = tid >> 2, acol = (tid & 3) << 2;
    int bs0 = blockIdx.y * 128;
    int bt0 = blockIdx.x * 128;
    float acc[8][8];
    #pragma unroll
    for (int i = 0; i < 8; i++)
        #pragma unroll
        for (int j = 0; j < 8; j++) acc[i][j] = 0.f;

    for (int k0 = 0; k0 < HDIM; k0 += 16) {
        float4 q0 = *(const float4*)(qb + (size_t)(bs0 + arow) * (3 * DD) + k0 + acol);
        float4 q1 = *(const float4*)(qb + (size_t)(bs0 + arow + 64) * (3 * DD) + k0 + acol);
        float4 c0 = *(const float4*)(kb + (size_t)(bt0 + arow) * (3 * DD) + k0 + acol);
        float4 c1 = *(const float4*)(kb + (size_t)(bt0 + arow + 64) * (3 * DD) + k0 + acol);
        __syncthreads();
        Qs[acol + 0][arow] = q0.x; Qs[acol + 1][arow] = q0.y;
        Qs[acol + 2][arow] = q0.z; Qs[acol + 3][arow] = q0.w;
        Qs[acol + 0][arow + 64] = q1.x; Qs[acol + 1][arow + 64] = q1.y;
        Qs[acol + 2][arow + 64] = q1.z; Qs[acol + 3][arow + 64] = q1.w;
        Ks[acol + 0][arow] = c0.x; Ks[acol + 1][arow] = c0.y;
        Ks[acol + 2][arow] = c0.z; Ks[acol + 3][arow] = c0.w;
        Ks[acol + 0][arow + 64] = c1.x; Ks[acol + 1][arow + 64] = c1.y;
        Ks[acol + 2][arow + 64] = c1.z; Ks[acol + 3][arow + 64] = c1.w;
        __syncthreads();
        #pragma unroll
        for (int k = 0; k < 16; k++) {
            float ra[8], rb[8];
            #pragma unroll
            for (int i = 0; i < 8; i++) ra[i] = Qs[k][ty * 8 + i];
            #pragma unroll
            for (int j = 0; j < 8; j++) rb[j] = Ks[k][tx * 8 + j];
            #pragma unroll
            for (int i = 0; i < 8; i++)
                #pragma unroll
                for (int j = 0; j < 8; j++) acc[i][j] = fmaf(ra[i], rb[j], acc[i][j]);
        }
    }
    float* base = scores + (size_t)bh * SS * SS;
    #pragma unroll
    for (int i = 0; i < 8; i++) {
        float* crow = base + (size_t)(bs0 + ty * 8 + i) * SS + bt0 + tx * 8;
        #pragma unroll
        for (int j4 = 0; j4 < 2; j4++) {
            float4 v;
            v.x = acc[i][j4 * 4 + 0]; v.y = acc[i][j4 * 4 + 1];
            v.z = acc[i][j4 * 4 + 2]; v.w = acc[i][j4 * 4 + 3];
            *(float4*)(crow + j4 * 4) = v;
        }
    }
}

// ---------------- softmax over t with scale + mask ----------------
// grid: B*H*S blocks, block 256, 4 elems/thread
__global__ __launch_bounds__(256) void softmax_kernel(float* __restrict__ scores,
                                                      const float* __restrict__ mask) {
    __shared__ float sh[8];
    size_t r = blockIdx.x;
    int bh = (int)(r >> 10);
    int s = (int)(r & 1023);
    int b = bh >> 4;
    float* row = scores + r * (size_t)SS;
    const float* mrow = mask + ((size_t)b * SS + s) * SS;
    int t0 = threadIdx.x * 4;
    float4 v4 = *(const float4*)(row + t0);
    float4 m4 = *(const float4*)(mrow + t0);
    const float scl = 0.125f;  // 1/sqrt(64)
    float v[4] = { v4.x * scl + m4.x, v4.y * scl + m4.y,
                   v4.z * scl + m4.z, v4.w * scl + m4.w };
    float mx = fmaxf(fmaxf(v[0], v[1]), fmaxf(v[2], v[3]));
    mx = blockReduceMax(mx, sh);
    float sum = 0.f;
    #pragma unroll
    for (int e = 0; e < 4; e++) { v[e] = __expf(v[e] - mx); sum += v[e]; }
    sum = blockReduceSum(sum, sh);
    float inv = 1.f / sum;
    float4 o; o.x = v[0] * inv; o.y = v[1] * inv; o.z = v[2] * inv; o.w = v[3] * inv;
    *(float4*)(row + t0) = o;
}

// ---------------- vals = attn @ v per (b,h), written to [B,S,H*HD] ----------------
// grid: (1, 8, 64), block 256; M-tile 128, N = 64, K = 1024
__global__ __launch_bounds__(256) void attnv_gemm(const float* __restrict__ scores,
                                                  const float* __restrict__ qkv,
                                                  float* __restrict__ vals) {
    __shared__ float As[16][132];
    __shared__ float Vs[16][64];
    int bh = blockIdx.z;
    int b = bh >> 4, h = bh & 15;
    const float* abase = scores + (size_t)bh * SS * SS;
    const float* vb = qkv + (size_t)b * SS * (3 * DD) + h * (3 * HDIM) + 2 * HDIM;
    int bm = blockIdx.y * 128;
    int tid = threadIdx.x;
    int tx = tid & 15, ty = tid >> 4;
    int la_row = tid >> 2, la_col = (tid & 3) << 2;   // attn tile loader
    int lb_row = tid >> 4, lb_col = (tid & 15) << 2;  // v tile loader: 16x64
    float acc[8][4];
    #pragma unroll
    for (int i = 0; i < 8; i++)
        #pragma unroll
        for (int j = 0; j < 4; j++) acc[i][j] = 0.f;

    for (int k0 = 0; k0 < SS; k0 += 16) {
        float4 a0 = *(const float4*)(abase + (size_t)(bm + la_row) * SS + k0 + la_col);
        float4 a1 = *(const float4*)(abase + (size_t)(bm + la_row + 64) * SS + k0 + la_col);
        float4 v0 = *(const float4*)(vb + (size_t)(k0 + lb_row) * (3 * DD) + lb_col);
        __syncthreads();
        As[la_col + 0][la_row] = a0.x; As[la_col + 1][la_row] = a0.y;
        As[la_col + 2][la_row] = a0.z; As[la_col + 3][la_row] = a0.w;
        As[la_col + 0][la_row + 64] = a1.x; As[la_col + 1][la_row + 64] = a1.y;
        As[la_col + 2][la_row + 64] = a1.z; As[la_col + 3][la_row + 64] = a1.w;
        *(float4*)&Vs[lb_row][lb_col] = v0;
        __syncthreads();
        #pragma unroll
        for (int k = 0; k < 16; k++) {
            float ra[8], rb[4];
            #pragma unroll
            for (int i = 0; i < 8; i++) ra[i] = As[k][ty * 8 + i];
            #pragma unroll
            for (int j = 0; j < 4; j++) rb[j] = Vs[k][tx * 4 + j];
            #pragma unroll
            for (int i = 0; i < 8; i++)
                #pragma unroll
                for (int j = 0; j < 4; j++) acc[i][j] = fmaf(ra[i], rb[j], acc[i][j]);
        }
    }
    #pragma unroll
    for (int i = 0; i < 8; i++) {
        size_t row = (size_t)b * SS + bm + ty * 8 + i;
        float4 o; o.x = acc[i][0]; o.y = acc[i][1]; o.z = acc[i][2]; o.w = acc[i][3];
        *(float4*)(vals + row * DD + h * HDIM + tx * 4) = o;
    }
}

// ---------------- residual add + LayerNorm (two-pass) ----------------
// grid: 4096 blocks, block 256, 4 elems/thread
__global__ __launch_bounds__(256) void ln_kernel(const float* __restrict__ x,
                                                 const float* __restrict__ y,
                                                 const float* __restrict__ gamma,
                                                 const float* __restrict__ beta,
                                                 float* __restrict__ out) {
    __shared__ float sh[8];
    size_t row = blockIdx.x;
    int d0 = threadIdx.x * 4;
    float4 a = *(const float4*)(x + row * DD + d0);
    float4 b4 = *(const float4*)(y + row * DD + d0);
    float z[4] = { a.x + b4.x, a.y + b4.y, a.z + b4.z, a.w + b4.w };
    float s = z[0] + z[1] + z[2] + z[3];
    s = blockReduceSum(s, sh);
    float mean = s * (1.0f / DD);
    float d2 = 0.f;
    #pragma unroll
    for (int e = 0; e < 4; e++) { float t = z[e] - mean; d2 += t * t; }
    d2 = blockReduceSum(d2, sh);
    float inv = rsqrtf(d2 * (1.0f / DD) + EPSV);
    float4 g4 = *(const float4*)(gamma + d0);
    float4 be4 = *(const float4*)(beta + d0);
    float4 o;
    o.x = g4.x * ((z[0] - mean) * inv) + be4.x;
    o.y = g4.y * ((z[1] - mean) * inv) + be4.y;
    o.z = g4.z * ((z[2] - mean) * inv) + be4.z;
    o.w = g4.w * ((z[3] - mean) * inv) + be4.w;
    *(float4*)(out + row * DD + d0) = o;
}

// ---------------- orchestration ----------------
extern "C" void kernel_launch(void* const* d_in, const int* in_sizes, int n_in,
                              void* d_out, int out_size) {
    const int*   tokens = (const int*)d_in[0];
    const float* mask   = (const float*)d_in[1];
    const float* emb    = (const float*)d_in[2];
    const float* qkv_w  = (const float*)d_in[3];
    const float* qkv_b  = (const float*)d_in[4];
    const float* out_w  = (const float*)d_in[5];
    const float* out_b  = (const float*)d_in[6];
    const float* w1     = (const float*)d_in[7];
    const float* b1     = (const float*)d_in[8];
    const float* w2     = (const float*)d_in[9];
    const float* b2     = (const float*)d_in[10];
    const float* gamma  = (const float*)d_in[11];
    const float* beta   = (const float*)d_in[12];
    float* out = (float*)d_out;

    float *px, *py, *pvals, *pqkv, *pff, *pscores;
    cudaGetSymbolAddress((void**)&px,     g_x);
    cudaGetSymbolAddress((void**)&py,     g_y);
    cudaGetSymbolAddress((void**)&pvals,  g_vals);
    cudaGetSymbolAddress((void**)&pqkv,   g_qkv);
    cudaGetSymbolAddress((void**)&pff,    g_ff);
    cudaGetSymbolAddress((void**)&pscores, g_scores);

    embed_kernel<<<MM, 256>>>(tokens, emb, px);

    for (int i = 0; i < LL; i++) {
        // QKV projection: [4096,1024] @ [1024,3072]
        gemm_nn<0><<<dim3(3 * DD / 128, MM / 128), 256>>>(
            px, DD, qkv_w + (size_t)i * DD * 3 * DD, 3 * DD,
            qkv_b + (size_t)i * 3 * DD, pqkv, 3 * DD, DD);
        // attention scores
        scores_gemm<<<dim3(SS / 128, SS / 128, BB * HH), 256>>>(pqkv, pscores);
        // softmax (scale + mask inside)
        softmax_kernel<<<BB * HH * SS, 256>>>(pscores, mask);
        // attn @ V
        attnv_gemm<<<dim3(1, SS / 128, BB * HH), 256>>>(pscores, pqkv, pvals);
        // output projection
        gemm_nn<0><<<dim3(DD / 128, MM / 128), 256>>>(
            pvals, DD, out_w + (size_t)i * DD * DD, DD,
            out_b + (size_t)i * DD, py, DD, DD);
        // x = LN(x + attn_out)
        ln_kernel<<<MM, 256>>>(px, py, gamma + (size_t)i * DD, beta + (size_t)i * DD, px);
        // FFN up (+ReLU): [4096,1024] @ [1024,4096]
        gemm_nn<1><<<dim3(FF / 128, MM / 128), 256>>>(
            px, DD, w1 + (size_t)i * DD * FF, FF,
            b1 + (size_t)i * FF, pff, FF, DD);
        // FFN down: [4096,4096] @ [4096,1024]
        gemm_nn<0><<<dim3(DD / 128, MM / 128), 256>>>(
            pff, FF, w2 + (size_t)i * FF * DD, DD,
            b2 + (size_t)i * DD, py, DD, FF);
        // x = LN(x + ff); last layer writes straight to d_out
        ln_kernel<<<MM, 256>>>(px, py, gamma + (size_t)i * DD, beta + (size_t)i * DD,
                               (i == LL - 1) ? out : px);
    }
}

// round 3
// speedup vs baseline: 1.7571x; 1.7571x over previous
#include <cuda_runtime.h>
#include <cuda_bf16.h>
#include <math.h>
#include <stdint.h>

#define BB 4
#define SS 1024
#define DD 1024
#define HH 16
#define HDIM 64
#define FF 4096
#define LL 6
#define MM (BB*SS)
#define EPSV 1e-5f

// ---------------- scratch (device globals; no allocation allowed) ----------------
__device__ float g_x[MM*DD];
__device__ float g_y[MM*DD];
__device__ float g_vals[MM*DD];
__device__ float g_qkv[MM*3*DD];
__device__ float g_ff[MM*FF];
__device__ float g_scores[(size_t)BB*HH*SS*SS];

// bf16 split buffers
__device__ __nv_bfloat16 g_ahi[MM*FF];
__device__ __nv_bfloat16 g_alo[MM*FF];
__device__ __nv_bfloat16 g_wqkv_hi[(size_t)LL*3*DD*DD];
__device__ __nv_bfloat16 g_wqkv_lo[(size_t)LL*3*DD*DD];
__device__ __nv_bfloat16 g_wout_hi[(size_t)LL*DD*DD];
__device__ __nv_bfloat16 g_wout_lo[(size_t)LL*DD*DD];
__device__ __nv_bfloat16 g_w1_hi[(size_t)LL*DD*FF];
__device__ __nv_bfloat16 g_w1_lo[(size_t)LL*DD*FF];
__device__ __nv_bfloat16 g_w2_hi[(size_t)LL*FF*DD];
__device__ __nv_bfloat16 g_w2_lo[(size_t)LL*FF*DD];

// ================= mma.sync building blocks (baseline PTX, no 'a' features) ======
__device__ __forceinline__ uint32_t smem_u32(const void* p) {
    return (uint32_t)__cvta_generic_to_shared((void*)p);
}
__device__ __forceinline__ void ldsm_x4(uint32_t (&r)[4], uint32_t addr) {
    asm volatile("ldmatrix.sync.aligned.m8n8.x4.shared.b16 {%0,%1,%2,%3}, [%4];"
        : "=r"(r[0]), "=r"(r[1]), "=r"(r[2]), "=r"(r[3]) : "r"(addr));
}
__device__ __forceinline__ void ldsm_x2(uint32_t (&r)[2], uint32_t addr) {
    asm volatile("ldmatrix.sync.aligned.m8n8.x2.shared.b16 {%0,%1}, [%2];"
        : "=r"(r[0]), "=r"(r[1]) : "r"(addr));
}
__device__ __forceinline__ void mma16816(float (&d)[4], const uint32_t (&a)[4],
                                         const uint32_t (&b)[2]) {
    asm volatile(
        "mma.sync.aligned.m16n8k16.row.col.f32.bf16.bf16.f32 "
        "{%0,%1,%2,%3}, {%4,%5,%6,%7}, {%8,%9}, {%0,%1,%2,%3};"
        : "+f"(d[0]), "+f"(d[1]), "+f"(d[2]), "+f"(d[3])
        : "r"(a[0]), "r"(a[1]), "r"(a[2]), "r"(a[3]), "r"(b[0]), "r"(b[1]));
}
__device__ __forceinline__ void cp16(uint32_t dst, const void* src) {
    asm volatile("cp.async.cg.shared.global [%0], [%1], 16;" :: "r"(dst), "l"(src));
}
#define CP_COMMIT() asm volatile("cp.async.commit_group;" ::: "memory")
#define CP_WAIT1()  asm volatile("cp.async.wait_group 1;" ::: "memory")
#define CP_WAIT0()  asm volatile("cp.async.wait_group 0;" ::: "memory")

// ================= tensor-core GEMM via mma.sync =================
// C[M,N] = A[M,K] @ W[K,N], bf16 3-split. A [M,K] hi/lo K-major; B [N,K] hi/lo K-major.
// CTA 128x128, BK=32, 256 threads (8 warps, 2x4), warp tile 64x32, 2-stage cp.async.
#define GBM 128
#define GBN 128
#define GBK 32
#define ROWB 80                    // bytes per smem row (32 bf16 + pad) -> conflict-free
#define TILEB (128*ROWB)           // 10240 bytes per array
#define STAGEB (4*TILEB)           // A_hi, A_lo, B_hi, B_lo
#define GT_SMEM (2*STAGEB)         // 81920 bytes

template<int RELU>
__global__ __launch_bounds__(256, 1) void gemm_mma(
    const __nv_bfloat16* __restrict__ Ahi, const __nv_bfloat16* __restrict__ Alo,
    const __nv_bfloat16* __restrict__ Bhi, const __nv_bfloat16* __restrict__ Blo,
    const float* __restrict__ bias, float* __restrict__ C, int N, int K)
{
    extern __shared__ char sm[];
    uint32_t sb = smem_u32(sm);
    int tid = threadIdx.x;
    int warp = tid >> 5, lane = tid & 31;
    int wm = warp >> 2, wn = warp & 3;                 // 2 x 4 warp grid
    int m0 = blockIdx.y * GBM, n0 = blockIdx.x * GBN;

    float acc[4][4][4];
    #pragma unroll
    for (int i = 0; i < 4; i++)
        #pragma unroll
        for (int j = 0; j < 4; j++)
            #pragma unroll
            for (int e = 0; e < 4; e++) acc[i][j][e] = 0.f;

    // loader: 512 16B-chunks per array per stage; thread handles chunks tid, tid+256
    int lrow0 = tid >> 2, lc0 = tid & 3;               // chunk tid
    int lrow1 = (tid + 256) >> 2, lc1 = lc0;           // chunk tid+256

    auto load_stage = [&](int s, int k0) {
        uint32_t base = sb + s * STAGEB;
        const __nv_bfloat16* ah = Ahi + (size_t)(m0 + lrow0) * K + k0 + lc0 * 8;
        const __nv_bfloat16* al = Alo + (size_t)(m0 + lrow0) * K + k0 + lc0 * 8;
        const __nv_bfloat16* bh = Bhi + (size_t)(n0 + lrow0) * K + k0 + lc0 * 8;
        const __nv_bfloat16* bl = Blo + (size_t)(n0 + lrow0) * K + k0 + lc0 * 8;
        uint32_t d0 = base + lrow0 * ROWB + lc0 * 16;
        cp16(d0,             ah);
        cp16(d0 + TILEB,     al);
        cp16(d0 + 2*TILEB,   bh);
        cp16(d0 + 3*TILEB,   bl);
        const __nv_bfloat16* ah1 = Ahi + (size_t)(m0 + lrow1) * K + k0 + lc1 * 8;
        const __nv_bfloat16* al1 = Alo + (size_t)(m0 + lrow1) * K + k0 + lc1 * 8;
        const __nv_bfloat16* bh1 = Bhi + (size_t)(n0 + lrow1) * K + k0 + lc1 * 8;
        const __nv_bfloat16* bl1 = Blo + (size_t)(n0 + lrow1) * K + k0 + lc1 * 8;
        uint32_t d1 = base + lrow1 * ROWB + lc1 * 16;
        cp16(d1,             ah1);
        cp16(d1 + TILEB,     al1);
        cp16(d1 + 2*TILEB,   bh1);
        cp16(d1 + 3*TILEB,   bl1);
    };

    int T = K / GBK;
    load_stage(0, 0);
    CP_COMMIT();

    // per-lane ldmatrix source addresses (within-tile parts)
    int a_r = lane & 15, a_c8 = (lane >> 4) * 8;       // A x4
    int b_r = lane & 7,  b_c8 = ((lane >> 3) & 1) * 8; // B x2 (lanes 0-15 used)

    for (int t = 0; t < T; t++) {
        if (t + 1 < T) {
            load_stage((t + 1) & 1, (t + 1) * GBK);
            CP_COMMIT();
            CP_WAIT1();
        } else {
            CP_WAIT0();
        }
        __syncthreads();

        uint32_t base = sb + (t & 1) * STAGEB;
        #pragma unroll
        for (int kk = 0; kk < 2; kk++) {
            uint32_t ah[4][4], al[4][4], bh[4][2], bl[4][2];
            #pragma unroll
            for (int mi = 0; mi < 4; mi++) {
                int row = wm * 64 + mi * 16 + a_r;
                uint32_t ad = base + row * ROWB + (kk * 16 + a_c8) * 2;
                ldsm_x4(ah[mi], ad);
                ldsm_x4(al[mi], ad + TILEB);
            }
            #pragma unroll
            for (int ni = 0; ni < 4; ni++) {
                int row = wn * 32 + ni * 8 + b_r;
                uint32_t bd = base + 2*TILEB + row * ROWB + (kk * 16 + b_c8) * 2;
                ldsm_x2(bh[ni], bd);
                ldsm_x2(bl[ni], bd + TILEB);
            }
            #pragma unroll
            for (int mi = 0; mi < 4; mi++)
                #pragma unroll
                for (int ni = 0; ni < 4; ni++) {
                    mma16816(acc[mi][ni], ah[mi], bh[ni]);
                    mma16816(acc[mi][ni], ah[mi], bl[ni]);
                    mma16816(acc[mi][ni], al[mi], bh[ni]);
                }
        }
        __syncthreads();
    }

    // epilogue: bias (+relu), fp32 store
    int qr = lane >> 2, qc = (lane & 3) * 2;
    #pragma unroll
    for (int mi = 0; mi < 4; mi++) {
        #pragma unroll
        for (int ni = 0; ni < 4; ni++) {
            int gr0 = m0 + wm * 64 + mi * 16 + qr;
            int gc  = n0 + wn * 32 + ni * 8 + qc;
            float b0 = bias[gc], b1 = bias[gc + 1];
            float2 v0 = make_float2(acc[mi][ni][0] + b0, acc[mi][ni][1] + b1);
            float2 v1 = make_float2(acc[mi][ni][2] + b0, acc[mi][ni][3] + b1);
            if (RELU) {
                v0.x = fmaxf(v0.x, 0.f); v0.y = fmaxf(v0.y, 0.f);
                v1.x = fmaxf(v1.x, 0.f); v1.y = fmaxf(v1.y, 0.f);
            }
            *(float2*)(C + (size_t)gr0 * N + gc)       = v0;
            *(float2*)(C + (size_t)(gr0 + 8) * N + gc) = v1;
        }
    }
}

// ================= split / transpose conversion kernels =================
__global__ __launch_bounds__(256) void split_bf16(const float* __restrict__ x,
                                                  __nv_bfloat16* __restrict__ hi,
                                                  __nv_bfloat16* __restrict__ lo, int n) {
    int i = (blockIdx.x * 256 + threadIdx.x) * 4;
    if (i >= n) return;
    float4 v = *(const float4*)(x + i);
    __nv_bfloat16 h0 = __float2bfloat16(v.x), h1 = __float2bfloat16(v.y);
    __nv_bfloat16 h2 = __float2bfloat16(v.z), h3 = __float2bfloat16(v.w);
    __nv_bfloat16 l0 = __float2bfloat16(v.x - __bfloat162float(h0));
    __nv_bfloat16 l1 = __float2bfloat16(v.y - __bfloat162float(h1));
    __nv_bfloat16 l2 = __float2bfloat16(v.z - __bfloat162float(h2));
    __nv_bfloat16 l3 = __float2bfloat16(v.w - __bfloat162float(h3));
    *(__nv_bfloat162*)(hi + i)     = __nv_bfloat162(h0, h1);
    *(__nv_bfloat162*)(hi + i + 2) = __nv_bfloat162(h2, h3);
    *(__nv_bfloat162*)(lo + i)     = __nv_bfloat162(l0, l1);
    *(__nv_bfloat162*)(lo + i + 2) = __nv_bfloat162(l2, l3);
}

// W [K,N] row-major fp32 -> [N,K] K-major bf16 hi/lo (per layer via blockIdx.z)
__global__ __launch_bounds__(256) void wsplit_t(const float* __restrict__ W,
                                                __nv_bfloat16* __restrict__ hi,
                                                __nv_bfloat16* __restrict__ lo,
                                                int Kdim, int Ndim) {
    __shared__ float t[32][33];
    size_t loff = (size_t)blockIdx.z * Kdim * Ndim;
    const float* Wl = W + loff;
    __nv_bfloat16* hil = hi + loff;
    __nv_bfloat16* lol = lo + loff;
    int k0 = blockIdx.y * 32, n0 = blockIdx.x * 32;
    int tx = threadIdx.x, ty = threadIdx.y;
    #pragma unroll
    for (int i = 0; i < 32; i += 8)
        t[ty + i][tx] = Wl[(size_t)(k0 + ty + i) * Ndim + n0 + tx];
    __syncthreads();
    #pragma unroll
    for (int i = 0; i < 32; i += 8) {
        int n = n0 + ty + i, k = k0 + tx;
        float v = t[tx][ty + i];
        __nv_bfloat16 h = __float2bfloat16(v);
        hil[(size_t)n * Kdim + k] = h;
        lol[(size_t)n * Kdim + k] = __float2bfloat16(v - __bfloat162float(h));
    }
}

// ================= fp32 helper kernels =================
__device__ __forceinline__ float warpReduceSum(float v) {
    #pragma unroll
    for (int o = 16; o; o >>= 1) v += __shfl_xor_sync(0xffffffffu, v, o);
    return v;
}
__device__ __forceinline__ float warpReduceMax(float v) {
    #pragma unroll
    for (int o = 16; o; o >>= 1) v = fmaxf(v, __shfl_xor_sync(0xffffffffu, v, o));
    return v;
}
__device__ __forceinline__ float blockReduceSum(float v, float* sh) {
    v = warpReduceSum(v);
    int w = threadIdx.x >> 5;
    __syncthreads();
    if ((threadIdx.x & 31) == 0) sh[w] = v;
    __syncthreads();
    if (threadIdx.x < 32) {
        float t = (threadIdx.x < 8) ? sh[threadIdx.x] : 0.f;
        t = warpReduceSum(t);
        if (threadIdx.x == 0) sh[0] = t;
    }
    __syncthreads();
    return sh[0];
}
__device__ __forceinline__ float blockReduceMax(float v, float* sh) {
    v = warpReduceMax(v);
    int w = threadIdx.x >> 5;
    __syncthreads();
    if ((threadIdx.x & 31) == 0) sh[w] = v;
    __syncthreads();
    if (threadIdx.x < 32) {
        float t = (threadIdx.x < 8) ? sh[threadIdx.x] : -INFINITY;
        t = warpReduceMax(t);
        if (threadIdx.x == 0) sh[0] = t;
    }
    __syncthreads();
    return sh[0];
}

__global__ __launch_bounds__(256) void embed_kernel(const int* __restrict__ tokens,
                                                    const float* __restrict__ emb,
                                                    float* __restrict__ x) {
    int row = blockIdx.x;
    int s = row & (SS - 1);
    int tok = tokens[row];
    const float* e = emb + (size_t)tok * DD;
    float* xr = x + (size_t)row * DD;
    for (int d = threadIdx.x; d < DD; d += 256) {
        int i2 = d & ~1;
        float denom = powf(10000.0f, (float)i2 / (float)DD);
        float ang = (float)s / denom;
        float pe = (d & 1) ? cosf(ang) : sinf(ang);
        xr[d] = e[d] + pe;
    }
}

__global__ __launch_bounds__(256) void scores_gemm(const float* __restrict__ qkv,
                                                   float* __restrict__ scores) {
    __shared__ float Qs[16][132];
    __shared__ float Ks[16][132];
    int bh = blockIdx.z;
    int b = bh >> 4, h = bh & 15;
    const float* qb = qkv + (size_t)b * SS * (3 * DD) + h * (3 * HDIM);
    const float* kb = qb + HDIM;
    int tid = threadIdx.x;
    int tx = tid & 15, ty = tid >> 4;
    int arow = tid >> 2, acol = (tid & 3) << 2;
    int bs0 = blockIdx.y * 128;
    int bt0 = blockIdx.x * 128;
    float acc[8][8];
    #pragma unroll
    for (int i = 0; i < 8; i++)
        #pragma unroll
        for (int j = 0; j < 8; j++) acc[i][j] = 0.f;
    for (int k0 = 0; k0 < HDIM; k0 += 16) {
        float4 q0 = *(const float4*)(qb + (size_t)(bs0 + arow) * (3 * DD) + k0 + acol);
        float4 q1 = *(const float4*)(qb + (size_t)(bs0 + arow + 64) * (3 * DD) + k0 + acol);
        float4 c0 = *(const float4*)(kb + (size_t)(bt0 + arow) * (3 * DD) + k0 + acol);
        float4 c1 = *(const float4*)(kb + (size_t)(bt0 + arow + 64) * (3 * DD) + k0 + acol);
        __syncthreads();
        Qs[acol + 0][arow] = q0.x; Qs[acol + 1][arow] = q0.y;
        Qs[acol + 2][arow] = q0.z; Qs[acol + 3][arow] = q0.w;
        Qs[acol + 0][arow + 64] = q1.x; Qs[acol + 1][arow + 64] = q1.y;
        Qs[acol + 2][arow + 64] = q1.z; Qs[acol + 3][arow + 64] = q1.w;
        Ks[acol + 0][arow] = c0.x; Ks[acol + 1][arow] = c0.y;
        Ks[acol + 2][arow] = c0.z; Ks[acol + 3][arow] = c0.w;
        Ks[acol + 0][arow + 64] = c1.x; Ks[acol + 1][arow + 64] = c1.y;
        Ks[acol + 2][arow + 64] = c1.z; Ks[acol + 3][arow + 64] = c1.w;
        __syncthreads();
        #pragma unroll
        for (int k = 0; k < 16; k++) {
            float ra[8], rb[8];
            #pragma unroll
            for (int i = 0; i < 8; i++) ra[i] = Qs[k][ty * 8 + i];
            #pragma unroll
            for (int j = 0; j < 8; j++) rb[j] = Ks[k][tx * 8 + j];
            #pragma unroll
            for (int i = 0; i < 8; i++)
                #pragma unroll
                for (int j = 0; j < 8; j++) acc[i][j] = fmaf(ra[i], rb[j], acc[i][j]);
        }
    }
    float* base = scores + (size_t)bh * SS * SS;
    #pragma unroll
    for (int i = 0; i < 8; i++) {
        float* crow = base + (size_t)(bs0 + ty * 8 + i) * SS + bt0 + tx * 8;
        #pragma unroll
        for (int j4 = 0; j4 < 2; j4++) {
            float4 v;
            v.x = acc[i][j4 * 4 + 0]; v.y = acc[i][j4 * 4 + 1];
            v.z = acc[i][j4 * 4 + 2]; v.w = acc[i][j4 * 4 + 3];
            *(float4*)(crow + j4 * 4) = v;
        }
    }
}

__global__ __launch_bounds__(256) void softmax_kernel(float* __restrict__ scores,
                                                      const float* __restrict__ mask) {
    __shared__ float sh[8];
    size_t r = blockIdx.x;
    int s = (int)(r & 1023);
    int b = (int)(r >> 14);
    float* row = scores + r * (size_t)SS;
    const float* mrow = mask + ((size_t)b * SS + s) * SS;
    int t0 = threadIdx.x * 4;
    float4 v4 = *(const float4*)(row + t0);
    float4 m4 = *(const float4*)(mrow + t0);
    const float scl = 0.125f;
    float v[4] = { v4.x * scl + m4.x, v4.y * scl + m4.y,
                   v4.z * scl + m4.z, v4.w * scl + m4.w };
    float mx = fmaxf(fmaxf(v[0], v[1]), fmaxf(v[2], v[3]));
    mx = blockReduceMax(mx, sh);
    float sum = 0.f;
    #pragma unroll
    for (int e = 0; e < 4; e++) { v[e] = __expf(v[e] - mx); sum += v[e]; }
    sum = blockReduceSum(sum, sh);
    float inv = 1.f / sum;
    float4 o; o.x = v[0] * inv; o.y = v[1] * inv; o.z = v[2] * inv; o.w = v[3] * inv;
    *(float4*)(row + t0) = o;
}

__global__ __launch_bounds__(256) void attnv_gemm(const float* __restrict__ scores,
                                                  const float* __restrict__ qkv,
                                                  float* __restrict__ vals) {
    __shared__ float As[16][132];
    __shared__ float Vs[16][64];
    int bh = blockIdx.z;
    int b = bh >> 4, h = bh & 15;
    const float* abase = scores + (size_t)bh * SS * SS;
    const float* vb = qkv + (size_t)b * SS * (3 * DD) + h * (3 * HDIM) + 2 * HDIM;
    int bm = blockIdx.y * 128;
    int tid = threadIdx.x;
    int tx = tid & 15, ty = tid >> 4;
    int la_row = tid >> 2, la_col = (tid & 3) << 2;
    int lb_row = tid >> 4, lb_col = (tid & 15) << 2;
    float acc[8][4];
    #pragma unroll
    for (int i = 0; i < 8; i++)
        #pragma unroll
        for (int j = 0; j < 4; j++) acc[i][j] = 0.f;
    for (int k0 = 0; k0 < SS; k0 += 16) {
        float4 a0 = *(const float4*)(abase + (size_t)(bm + la_row) * SS + k0 + la_col);
        float4 a1 = *(const float4*)(abase + (size_t)(bm + la_row + 64) * SS + k0 + la_col);
        float4 v0 = *(const float4*)(vb + (size_t)(k0 + lb_row) * (3 * DD) + lb_col);
        __syncthreads();
        As[la_col + 0][la_row] = a0.x; As[la_col + 1][la_row] = a0.y;
        As[la_col + 2][la_row] = a0.z; As[la_col + 3][la_row] = a0.w;
        As[la_col + 0][la_row + 64] = a1.x; As[la_col + 1][la_row + 64] = a1.y;
        As[la_col + 2][la_row + 64] = a1.z; As[la_col + 3][la_row + 64] = a1.w;
        *(float4*)&Vs[lb_row][lb_col] = v0;
        __syncthreads();
        #pragma unroll
        for (int k = 0; k < 16; k++) {
            float ra[8], rb[4];
            #pragma unroll
            for (int i = 0; i < 8; i++) ra[i] = As[k][ty * 8 + i];
            #pragma unroll
            for (int j = 0; j < 4; j++) rb[j] = Vs[k][tx * 4 + j];
            #pragma unroll
            for (int i = 0; i < 8; i++)
                #pragma unroll
                for (int j = 0; j < 4; j++) acc[i][j] = fmaf(ra[i], rb[j], acc[i][j]);
        }
    }
    #pragma unroll
    for (int i = 0; i < 8; i++) {
        size_t row = (size_t)b * SS + bm + ty * 8 + i;
        float4 o; o.x = acc[i][0]; o.y = acc[i][1]; o.z = acc[i][2]; o.w = acc[i][3];
        *(float4*)(vals + row * DD + h * HDIM + tx * 4) = o;
    }
}

__global__ __launch_bounds__(256) void ln_kernel(const float* __restrict__ x,
                                                 const float* __restrict__ y,
                                                 const float* __restrict__ gamma,
                                                 const float* __restrict__ beta,
                                                 float* __restrict__ out) {
    __shared__ float sh[8];
    size_t row = blockIdx.x;
    int d0 = threadIdx.x * 4;
    float4 a = *(const float4*)(x + row * DD + d0);
    float4 b4 = *(const float4*)(y + row * DD + d0);
    float z[4] = { a.x + b4.x, a.y + b4.y, a.z + b4.z, a.w + b4.w };
    float s = z[0] + z[1] + z[2] + z[3];
    s = blockReduceSum(s, sh);
    float mean = s * (1.0f / DD);
    float d2 = 0.f;
    #pragma unroll
    for (int e = 0; e < 4; e++) { float t = z[e] - mean; d2 += t * t; }
    d2 = blockReduceSum(d2, sh);
    float inv = rsqrtf(d2 * (1.0f / DD) + EPSV);
    float4 g4 = *(const float4*)(gamma + d0);
    float4 be4 = *(const float4*)(beta + d0);
    float4 o;
    o.x = g4.x * ((z[0] - mean) * inv) + be4.x;
    o.y = g4.y * ((z[1] - mean) * inv) + be4.y;
    o.z = g4.z * ((z[2] - mean) * inv) + be4.z;
    o.w = g4.w * ((z[3] - mean) * inv) + be4.w;
    *(float4*)(out + row * DD + d0) = o;
}

// ================= orchestration =================
extern "C" void kernel_launch(void* const* d_in, const int* in_sizes, int n_in,
                              void* d_out, int out_size) {
    const int*   tokens = (const int*)d_in[0];
    const float* mask   = (const float*)d_in[1];
    const float* emb    = (const float*)d_in[2];
    const float* qkv_w  = (const float*)d_in[3];
    const float* qkv_b  = (const float*)d_in[4];
    const float* out_w  = (const float*)d_in[5];
    const float* out_b  = (const float*)d_in[6];
    const float* w1     = (const float*)d_in[7];
    const float* b1     = (const float*)d_in[8];
    const float* w2     = (const float*)d_in[9];
    const float* b2     = (const float*)d_in[10];
    const float* gamma  = (const float*)d_in[11];
    const float* beta   = (const float*)d_in[12];
    float* out = (float*)d_out;

    float *px, *py, *pvals, *pqkv, *pff, *pscores;
    cudaGetSymbolAddress((void**)&px,      g_x);
    cudaGetSymbolAddress((void**)&py,      g_y);
    cudaGetSymbolAddress((void**)&pvals,   g_vals);
    cudaGetSymbolAddress((void**)&pqkv,    g_qkv);
    cudaGetSymbolAddress((void**)&pff,     g_ff);
    cudaGetSymbolAddress((void**)&pscores, g_scores);
    __nv_bfloat16 *pahi, *palo, *pqh, *pql, *poh, *pol, *p1h, *p1l, *p2h, *p2l;
    cudaGetSymbolAddress((void**)&pahi, g_ahi);
    cudaGetSymbolAddress((void**)&palo, g_alo);
    cudaGetSymbolAddress((void**)&pqh,  g_wqkv_hi);
    cudaGetSymbolAddress((void**)&pql,  g_wqkv_lo);
    cudaGetSymbolAddress((void**)&poh,  g_wout_hi);
    cudaGetSymbolAddress((void**)&pol,  g_wout_lo);
    cudaGetSymbolAddress((void**)&p1h,  g_w1_hi);
    cudaGetSymbolAddress((void**)&p1l,  g_w1_lo);
    cudaGetSymbolAddress((void**)&p2h,  g_w2_hi);
    cudaGetSymbolAddress((void**)&p2l,  g_w2_lo);

    cudaFuncSetAttribute(gemm_mma<0>, cudaFuncAttributeMaxDynamicSharedMemorySize, GT_SMEM);
    cudaFuncSetAttribute(gemm_mma<1>, cudaFuncAttributeMaxDynamicSharedMemorySize, GT_SMEM);

    // weight conversion: fp32 [K,N] -> bf16 hi/lo [N,K]
    wsplit_t<<<dim3(3 * DD / 32, DD / 32, LL), dim3(32, 8)>>>(qkv_w, pqh, pql, DD, 3 * DD);
    wsplit_t<<<dim3(DD / 32, DD / 32, LL),     dim3(32, 8)>>>(out_w, poh, pol, DD, DD);
    wsplit_t<<<dim3(FF / 32, DD / 32, LL),     dim3(32, 8)>>>(w1, p1h, p1l, DD, FF);
    wsplit_t<<<dim3(DD / 32, FF / 32, LL),     dim3(32, 8)>>>(w2, p2h, p2l, FF, DD);

    embed_kernel<<<MM, 256>>>(tokens, emb, px);

    for (int i = 0; i < LL; i++) {
        size_t l = (size_t)i;
        // QKV
        split_bf16<<<MM * DD / 1024, 256>>>(px, pahi, palo, MM * DD);
        gemm_mma<0><<<dim3(3 * DD / GBN, MM / GBM), 256, GT_SMEM>>>(
            pahi, palo, pqh + l * 3 * DD * DD, pql + l * 3 * DD * DD,
            qkv_b + l * 3 * DD, pqkv, 3 * DD, DD);
        // attention (fp32 SIMT)
        scores_gemm<<<dim3(SS / 128, SS / 128, BB * HH), 256>>>(pqkv, pscores);
        softmax_kernel<<<BB * HH * SS, 256>>>(pscores, mask);
        attnv_gemm<<<dim3(1, SS / 128, BB * HH), 256>>>(pscores, pqkv, pvals);
        // out projection
        split_bf16<<<MM * DD / 1024, 256>>>(pvals, pahi, palo, MM * DD);
        gemm_mma<0><<<dim3(DD / GBN, MM / GBM), 256, GT_SMEM>>>(
            pahi, palo, poh + l * DD * DD, pol + l * DD * DD,
            out_b + l * DD, py, DD, DD);
        ln_kernel<<<MM, 256>>>(px, py, gamma + l * DD, beta + l * DD, px);
        // FFN up (+ReLU)
        split_bf16<<<MM * DD / 1024, 256>>>(px, pahi, palo, MM * DD);
        gemm_mma<1><<<dim3(FF / GBN, MM / GBM), 256, GT_SMEM>>>(
            pahi, palo, p1h + l * DD * FF, p1l + l * DD * FF,
            b1 + l * FF, pff, FF, DD);
        // FFN down
        split_bf16<<<MM * FF / 1024, 256>>>(pff, pahi, palo, MM * FF);
        gemm_mma<0><<<dim3(DD / GBN, MM / GBM), 256, GT_SMEM>>>(
            pahi, palo, p2h + l * FF * DD, p2l + l * FF * DD,
            b2 + l * DD, py, DD, FF);
        ln_kernel<<<MM, 256>>>(px, py, gamma + l * DD, beta + l * DD,
                               (i == LL - 1) ? out : px);
    }
}

// round 4
// speedup vs baseline: 2.2974x; 1.3075x over previous
#include <cuda_runtime.h>
#include <cuda_bf16.h>
#include <math.h>
#include <stdint.h>

#define BB 4
#define SS 1024
#define DD 1024
#define HH 16
#define HDIM 64
#define FF 4096
#define LL 6
#define MM (BB*SS)
#define EPSV 1e-5f

// ---------------- scratch (device globals; no allocation allowed) ----------------
__device__ float g_x[MM*DD];
__device__ float g_y[MM*DD];
__device__ __nv_bfloat16 g_ahi[MM*DD];
__device__ __nv_bfloat16 g_alo[MM*DD];
__device__ __nv_bfloat16 g_ffh[MM*FF];
__device__ __nv_bfloat16 g_ffl[MM*FF];
__device__ __nv_bfloat16 g_qh[BB*HH*SS*HDIM];
__device__ __nv_bfloat16 g_ql[BB*HH*SS*HDIM];
__device__ __nv_bfloat16 g_kh[BB*HH*SS*HDIM];
__device__ __nv_bfloat16 g_kl[BB*HH*SS*HDIM];
__device__ __nv_bfloat16 g_vh[BB*HH*SS*HDIM];
__device__ __nv_bfloat16 g_vl[BB*HH*SS*HDIM];
__device__ __nv_bfloat16 g_voh[MM*DD];
__device__ __nv_bfloat16 g_vol[MM*DD];
// weights
__device__ __nv_bfloat16 g_wqkv_hi[(size_t)LL*3*DD*DD];
__device__ __nv_bfloat16 g_wqkv_lo[(size_t)LL*3*DD*DD];
__device__ __nv_bfloat16 g_wout_hi[(size_t)LL*DD*DD];
__device__ __nv_bfloat16 g_wout_lo[(size_t)LL*DD*DD];
__device__ __nv_bfloat16 g_w1_hi[(size_t)LL*DD*FF];
__device__ __nv_bfloat16 g_w1_lo[(size_t)LL*DD*FF];
__device__ __nv_bfloat16 g_w2_hi[(size_t)LL*FF*DD];
__device__ __nv_bfloat16 g_w2_lo[(size_t)LL*FF*DD];

// ================= PTX building blocks =================
__device__ __forceinline__ uint32_t smem_u32(const void* p) {
    return (uint32_t)__cvta_generic_to_shared((void*)p);
}
__device__ __forceinline__ void ldsm_x4(uint32_t (&r)[4], uint32_t addr) {
    asm volatile("ldmatrix.sync.aligned.m8n8.x4.shared.b16 {%0,%1,%2,%3}, [%4];"
        : "=r"(r[0]), "=r"(r[1]), "=r"(r[2]), "=r"(r[3]) : "r"(addr));
}
__device__ __forceinline__ void ldsm_x4_t(uint32_t (&r)[4], uint32_t addr) {
    asm volatile("ldmatrix.sync.aligned.m8n8.x4.trans.shared.b16 {%0,%1,%2,%3}, [%4];"
        : "=r"(r[0]), "=r"(r[1]), "=r"(r[2]), "=r"(r[3]) : "r"(addr));
}
__device__ __forceinline__ void ldsm_x2(uint32_t (&r)[2], uint32_t addr) {
    asm volatile("ldmatrix.sync.aligned.m8n8.x2.shared.b16 {%0,%1}, [%2];"
        : "=r"(r[0]), "=r"(r[1]) : "r"(addr));
}
__device__ __forceinline__ void mma16816(float (&d)[4], const uint32_t (&a)[4],
                                         const uint32_t (&b)[2]) {
    asm volatile(
        "mma.sync.aligned.m16n8k16.row.col.f32.bf16.bf16.f32 "
        "{%0,%1,%2,%3}, {%4,%5,%6,%7}, {%8,%9}, {%0,%1,%2,%3};"
        : "+f"(d[0]), "+f"(d[1]), "+f"(d[2]), "+f"(d[3])
        : "r"(a[0]), "r"(a[1]), "r"(a[2]), "r"(a[3]), "r"(b[0]), "r"(b[1]));
}
__device__ __forceinline__ void mma16816b(float (&d)[4], const uint32_t (&a)[4],
                                          uint32_t b0, uint32_t b1) {
    asm volatile(
        "mma.sync.aligned.m16n8k16.row.col.f32.bf16.bf16.f32 "
        "{%0,%1,%2,%3}, {%4,%5,%6,%7}, {%8,%9}, {%0,%1,%2,%3};"
        : "+f"(d[0]), "+f"(d[1]), "+f"(d[2]), "+f"(d[3])
        : "r"(a[0]), "r"(a[1]), "r"(a[2]), "r"(a[3]), "r"(b0), "r"(b1));
}
__device__ __forceinline__ void cp16(uint32_t dst, const void* src) {
    asm volatile("cp.async.cg.shared.global [%0], [%1], 16;" :: "r"(dst), "l"(src));
}
#define CP_COMMIT() asm volatile("cp.async.commit_group;" ::: "memory")
#define CP_WAIT1()  asm volatile("cp.async.wait_group 1;" ::: "memory")
#define CP_WAIT0()  asm volatile("cp.async.wait_group 0;" ::: "memory")

__device__ __forceinline__ void store_hilo(__nv_bfloat16* ph, __nv_bfloat16* pl,
                                           size_t idx, float a, float b) {
    __nv_bfloat16 ha = __float2bfloat16(a), hb = __float2bfloat16(b);
    __nv_bfloat162 h2(ha, hb);
    *(__nv_bfloat162*)(ph + idx) = h2;
    __nv_bfloat162 l2(__float2bfloat16(a - __bfloat162float(ha)),
                      __float2bfloat16(b - __bfloat162float(hb)));
    *(__nv_bfloat162*)(pl + idx) = l2;
}
__device__ __forceinline__ void split2(float a, float b, uint32_t& hi, uint32_t& lo) {
    __nv_bfloat16 ha = __float2bfloat16(a), hb = __float2bfloat16(b);
    __nv_bfloat162 h2(ha, hb);
    hi = *(uint32_t*)&h2;
    __nv_bfloat162 l2(__float2bfloat16(a - __bfloat162float(ha)),
                      __float2bfloat16(b - __bfloat162float(hb)));
    lo = *(uint32_t*)&l2;
}

// ================= tensor-core GEMM via mma.sync =================
// C[M,N] = A[M,K] @ W[K,N], bf16 3-split. EPI: 0 = fp32 C; 1 = bf16 hi/lo + ReLU;
// 2 = QKV scatter to g_q/g_k/g_v hi/lo (q scaled by 1/8).
#define GBM 128
#define GBN 128
#define GBK 32
#define ROWB 80
#define TILEB (128*ROWB)
#define STAGEB (4*TILEB)
#define GT_SMEM (2*STAGEB)

template<int EPI>
__global__ __launch_bounds__(256, 1) void gemm_mma(
    const __nv_bfloat16* __restrict__ Ahi, const __nv_bfloat16* __restrict__ Alo,
    const __nv_bfloat16* __restrict__ Bhi, const __nv_bfloat16* __restrict__ Blo,
    const float* __restrict__ bias, float* __restrict__ Cf,
    __nv_bfloat16* __restrict__ Ch, __nv_bfloat16* __restrict__ Cl,
    int N, int K)
{
    extern __shared__ char sm[];
    uint32_t sb = smem_u32(sm);
    int tid = threadIdx.x;
    int warp = tid >> 5, lane = tid & 31;
    int wm = warp >> 2, wn = warp & 3;
    int m0 = blockIdx.y * GBM, n0 = blockIdx.x * GBN;

    float acc[4][4][4];
    #pragma unroll
    for (int i = 0; i < 4; i++)
        #pragma unroll
        for (int j = 0; j < 4; j++)
            #pragma unroll
            for (int e = 0; e < 4; e++) acc[i][j][e] = 0.f;

    int lrow0 = tid >> 2, lc0 = tid & 3;
    int lrow1 = (tid + 256) >> 2;

    auto load_stage = [&](int s, int k0) {
        uint32_t base = sb + s * STAGEB;
        uint32_t d0 = base + lrow0 * ROWB + lc0 * 16;
        cp16(d0,           Ahi + (size_t)(m0 + lrow0) * K + k0 + lc0 * 8);
        cp16(d0 + TILEB,   Alo + (size_t)(m0 + lrow0) * K + k0 + lc0 * 8);
        cp16(d0 + 2*TILEB, Bhi + (size_t)(n0 + lrow0) * K + k0 + lc0 * 8);
        cp16(d0 + 3*TILEB, Blo + (size_t)(n0 + lrow0) * K + k0 + lc0 * 8);
        uint32_t d1 = base + lrow1 * ROWB + lc0 * 16;
        cp16(d1,           Ahi + (size_t)(m0 + lrow1) * K + k0 + lc0 * 8);
        cp16(d1 + TILEB,   Alo + (size_t)(m0 + lrow1) * K + k0 + lc0 * 8);
        cp16(d1 + 2*TILEB, Bhi + (size_t)(n0 + lrow1) * K + k0 + lc0 * 8);
        cp16(d1 + 3*TILEB, Blo + (size_t)(n0 + lrow1) * K + k0 + lc0 * 8);
    };

    int T = K / GBK;
    load_stage(0, 0);
    CP_COMMIT();

    int a_r = lane & 15, a_c8 = (lane >> 4) * 8;
    int b_r = lane & 7,  b_c8 = ((lane >> 3) & 1) * 8;

    for (int t = 0; t < T; t++) {
        if (t + 1 < T) {
            load_stage((t + 1) & 1, (t + 1) * GBK);
            CP_COMMIT();
            CP_WAIT1();
        } else {
            CP_WAIT0();
        }
        __syncthreads();

        uint32_t base = sb + (t & 1) * STAGEB;
        #pragma unroll
        for (int kk = 0; kk < 2; kk++) {
            uint32_t ah[4][4], al[4][4], bh[4][2], bl[4][2];
            #pragma unroll
            for (int mi = 0; mi < 4; mi++) {
                int row = wm * 64 + mi * 16 + a_r;
                uint32_t ad = base + row * ROWB + (kk * 16 + a_c8) * 2;
                ldsm_x4(ah[mi], ad);
                ldsm_x4(al[mi], ad + TILEB);
            }
            #pragma unroll
            for (int ni = 0; ni < 4; ni++) {
                int row = wn * 32 + ni * 8 + b_r;
                uint32_t bd = base + 2*TILEB + row * ROWB + (kk * 16 + b_c8) * 2;
                ldsm_x2(bh[ni], bd);
                ldsm_x2(bl[ni], bd + TILEB);
            }
            #pragma unroll
            for (int mi = 0; mi < 4; mi++)
                #pragma unroll
                for (int ni = 0; ni < 4; ni++) {
                    mma16816(acc[mi][ni], ah[mi], bh[ni]);
                    mma16816(acc[mi][ni], ah[mi], bl[ni]);
                    mma16816(acc[mi][ni], al[mi], bh[ni]);
                }
        }
        __syncthreads();
    }

    int qr = lane >> 2, qc = (lane & 3) * 2;
    #pragma unroll
    for (int mi = 0; mi < 4; mi++) {
        #pragma unroll
        for (int ni = 0; ni < 4; ni++) {
            int gr = m0 + wm * 64 + mi * 16 + qr;
            int gc = n0 + wn * 32 + ni * 8 + qc;
            float b0 = bias[gc], b1 = bias[gc + 1];
            float v00 = acc[mi][ni][0] + b0, v01 = acc[mi][ni][1] + b1;
            float v10 = acc[mi][ni][2] + b0, v11 = acc[mi][ni][3] + b1;
            if (EPI == 0) {
                *(float2*)(Cf + (size_t)gr * N + gc)       = make_float2(v00, v01);
                *(float2*)(Cf + (size_t)(gr + 8) * N + gc) = make_float2(v10, v11);
            } else if (EPI == 1) {
                v00 = fmaxf(v00, 0.f); v01 = fmaxf(v01, 0.f);
                v10 = fmaxf(v10, 0.f); v11 = fmaxf(v11, 0.f);
                store_hilo(Ch, Cl, (size_t)gr * N + gc,       v00, v01);
                store_hilo(Ch, Cl, (size_t)(gr + 8) * N + gc, v10, v11);
            } else {
                int hh = gc / 192, inner = gc - hh * 192;
                int ty = inner >> 6, d = inner & 63;
                if (ty == 0) { v00 *= 0.125f; v01 *= 0.125f; v10 *= 0.125f; v11 *= 0.125f; }
                __nv_bfloat16* ph = (ty == 0) ? g_qh : (ty == 1) ? g_kh : g_vh;
                __nv_bfloat16* pl = (ty == 0) ? g_ql : (ty == 1) ? g_kl : g_vl;
                int bb = gr >> 10, si = gr & 1023;
                size_t dst = ((size_t)(bb * HH + hh) * SS + si) * HDIM + d;
                store_hilo(ph, pl, dst,            v00, v01);
                store_hilo(ph, pl, dst + 8 * HDIM, v10, v11);
            }
        }
    }
}

// ================= flash attention (fused scores+softmax+PV) =================
// grid (8 qtiles, 64 bh), 256 threads; warp w owns q-rows 16w..16w+15.
#define FA_ROWF 144
#define FA_TILE (128*FA_ROWF)
#define FA_STAGE (4*FA_TILE)
#define FA_SMEM (2*FA_STAGE)

__global__ __launch_bounds__(256, 1) void flash_attn(const float* __restrict__ mask)
{
    extern __shared__ char sm[];
    uint32_t sb = smem_u32(sm);
    int tid = threadIdx.x, lane = tid & 31, w = tid >> 5;
    int qt = blockIdx.x, bh = blockIdx.y;
    int b = bh >> 4, h = bh & 15;
    size_t head = (size_t)bh * SS * HDIM;

    // ---- stage Q (hi->tile0, lo->tile1 of stage0) ----
    #pragma unroll
    for (int j = 0; j < 8; j++) {
        int ch = tid + 256 * j;
        int tile = ch >> 10, row = (ch >> 3) & 127, c = ch & 7;
        const __nv_bfloat16* src = (tile ? g_ql : g_qh) + head
                                   + (size_t)(qt * 128 + row) * HDIM + c * 8;
        cp16(sb + tile * FA_TILE + row * FA_ROWF + c * 16, src);
    }
    CP_COMMIT(); CP_WAIT0();
    __syncthreads();

    uint32_t qfh[4][4], qfl[4][4];
    {
        int ar = lane & 15, ac = (lane >> 4) * 8;
        #pragma unroll
        for (int kb = 0; kb < 4; kb++) {
            uint32_t ad = sb + (w * 16 + ar) * FA_ROWF + (kb * 16 + ac) * 2;
            ldsm_x4(qfh[kb], ad);
            ldsm_x4(qfl[kb], ad + FA_TILE);
        }
    }
    __syncthreads();

    auto load_kv = [&](int s, int kt) {
        uint32_t base = sb + s * FA_STAGE;
        size_t goff = head + (size_t)(kt * 128) * HDIM;
        #pragma unroll
        for (int j = 0; j < 16; j++) {
            int ch = tid + 256 * j;
            int tile = ch >> 10, row = (ch >> 3) & 127, c = ch & 7;
            const __nv_bfloat16* sp = (tile == 0) ? g_kh : (tile == 1) ? g_kl
                                     : (tile == 2) ? g_vh : g_vl;
            cp16(base + tile * FA_TILE + row * FA_ROWF + c * 16,
                 sp + goff + (size_t)row * HDIM + c * 8);
        }
    };
    load_kv(0, 0);
    CP_COMMIT();

    int g = lane >> 2, t = lane & 3;
    int krow = (lane & 7) + ((lane >> 4) & 1) * 8, kcol = ((lane >> 3) & 1) * 8;
    int vrow = (lane & 7) + ((lane >> 3) & 1) * 8, vcol = ((lane >> 4) & 1) * 8;
    int qrow0 = qt * 128 + w * 16 + g;
    const float* mrow0 = mask + ((size_t)(b * SS + qrow0)) * SS;

    float m0v = -1e30f, m1v = -1e30f, l0v = 0.f, l1v = 0.f;
    float o[8][4];
    #pragma unroll
    for (int nf = 0; nf < 8; nf++)
        #pragma unroll
        for (int e = 0; e < 4; e++) o[nf][e] = 0.f;

    for (int kt = 0; kt < 8; kt++) {
        if (kt < 7) { load_kv((kt + 1) & 1, kt + 1); CP_COMMIT(); CP_WAIT1(); }
        else CP_WAIT0();
        __syncthreads();
        uint32_t base = sb + (kt & 1) * FA_STAGE;

        // ---- S = Q K^T (3-term split) ----
        float s[16][4];
        #pragma unroll
        for (int np = 0; np < 8; np++) {
            #pragma unroll
            for (int e = 0; e < 4; e++) { s[2*np][e] = 0.f; s[2*np+1][e] = 0.f; }
            #pragma unroll
            for (int kb = 0; kb < 4; kb++) {
                uint32_t ka = base + (np * 16 + krow) * FA_ROWF + (kb * 16 + kcol) * 2;
                uint32_t kh4[4], kl4[4];
                ldsm_x4(kh4, ka);
                ldsm_x4(kl4, ka + FA_TILE);
                mma16816b(s[2*np],   qfh[kb], kh4[0], kh4[1]);
                mma16816b(s[2*np+1], qfh[kb], kh4[2], kh4[3]);
                mma16816b(s[2*np],   qfh[kb], kl4[0], kl4[1]);
                mma16816b(s[2*np+1], qfh[kb], kl4[2], kl4[3]);
                mma16816b(s[2*np],   qfl[kb], kh4[0], kh4[1]);
                mma16816b(s[2*np+1], qfl[kb], kh4[2], kh4[3]);
            }
        }

        // ---- mask + online softmax (q pre-scaled by 1/8) ----
        float mx0 = -1e30f, mx1 = -1e30f;
        #pragma unroll
        for (int ni = 0; ni < 16; ni++) {
            const float* mp = mrow0 + kt * 128 + ni * 8 + 2 * t;
            float2 mk0 = *(const float2*)mp;
            float2 mk1 = *(const float2*)(mp + 8 * SS);
            s[ni][0] += mk0.x; s[ni][1] += mk0.y;
            s[ni][2] += mk1.x; s[ni][3] += mk1.y;
            mx0 = fmaxf(mx0, fmaxf(s[ni][0], s[ni][1]));
            mx1 = fmaxf(mx1, fmaxf(s[ni][2], s[ni][3]));
        }
        mx0 = fmaxf(mx0, __shfl_xor_sync(0xffffffffu, mx0, 1));
        mx0 = fmaxf(mx0, __shfl_xor_sync(0xffffffffu, mx0, 2));
        mx1 = fmaxf(mx1, __shfl_xor_sync(0xffffffffu, mx1, 1));
        mx1 = fmaxf(mx1, __shfl_xor_sync(0xffffffffu, mx1, 2));
        float mn0 = fmaxf(m0v, mx0), mn1 = fmaxf(m1v, mx1);
        float a0 = __expf(m0v - mn0), a1 = __expf(m1v - mn1);
        m0v = mn0; m1v = mn1;
        l0v *= a0; l1v *= a1;
        #pragma unroll
        for (int nf = 0; nf < 8; nf++) {
            o[nf][0] *= a0; o[nf][1] *= a0; o[nf][2] *= a1; o[nf][3] *= a1;
        }
        #pragma unroll
        for (int ni = 0; ni < 16; ni++) {
            s[ni][0] = __expf(s[ni][0] - mn0); s[ni][1] = __expf(s[ni][1] - mn0);
            s[ni][2] = __expf(s[ni][2] - mn1); s[ni][3] = __expf(s[ni][3] - mn1);
            l0v += s[ni][0] + s[ni][1];
            l1v += s[ni][2] + s[ni][3];
        }

        // ---- O += P V (P hi/lo re-pack, V via ldmatrix.trans) ----
        #pragma unroll
        for (int ks = 0; ks < 8; ks++) {
            uint32_t pah[4], pal[4];
            split2(s[2*ks][0],   s[2*ks][1],   pah[0], pal[0]);
            split2(s[2*ks][2],   s[2*ks][3],   pah[1], pal[1]);
            split2(s[2*ks+1][0], s[2*ks+1][1], pah[2], pal[2]);
            split2(s[2*ks+1][2], s[2*ks+1][3], pah[3], pal[3]);
            #pragma unroll
            for (int nv = 0; nv < 4; nv++) {
                uint32_t va = base + 2*FA_TILE + (ks * 16 + vrow) * FA_ROWF
                              + (nv * 16 + vcol) * 2;
                uint32_t vh4[4], vl4[4];
                ldsm_x4_t(vh4, va);
                ldsm_x4_t(vl4, va + FA_TILE);
                mma16816b(o[2*nv],   pah, vh4[0], vh4[1]);
                mma16816b(o[2*nv+1], pah, vh4[2], vh4[3]);
                mma16816b(o[2*nv],   pah, vl4[0], vl4[1]);
                mma16816b(o[2*nv+1], pah, vl4[2], vl4[3]);
                mma16816b(o[2*nv],   pal, vh4[0], vh4[1]);
                mma16816b(o[2*nv+1], pal, vh4[2], vh4[3]);
            }
        }
        __syncthreads();
    }

    // ---- finalize: 1/l, write hi/lo bf16 into [B*S, D] layout ----
    l0v += __shfl_xor_sync(0xffffffffu, l0v, 1);
    l0v += __shfl_xor_sync(0xffffffffu, l0v, 2);
    l1v += __shfl_xor_sync(0xffffffffu, l1v, 1);
    l1v += __shfl_xor_sync(0xffffffffu, l1v, 2);
    float inv0 = 1.f / l0v, inv1 = 1.f / l1v;
    size_t orow0 = (size_t)(b * SS + qrow0) * DD + h * HDIM;
    size_t orow1 = orow0 + (size_t)8 * DD;
    #pragma unroll
    for (int nf = 0; nf < 8; nf++) {
        int col = nf * 8 + 2 * t;
        store_hilo(g_voh, g_vol, orow0 + col, o[nf][0] * inv0, o[nf][1] * inv0);
        store_hilo(g_voh, g_vol, orow1 + col, o[nf][2] * inv1, o[nf][3] * inv1);
    }
}

// ================= weight transpose+split =================
__global__ __launch_bounds__(256) void wsplit_t(const float* __restrict__ W,
                                                __nv_bfloat16* __restrict__ hi,
                                                __nv_bfloat16* __restrict__ lo,
                                                int Kdim, int Ndim) {
    __shared__ float t[32][33];
    size_t loff = (size_t)blockIdx.z * Kdim * Ndim;
    const float* Wl = W + loff;
    __nv_bfloat16* hil = hi + loff;
    __nv_bfloat16* lol = lo + loff;
    int k0 = blockIdx.y * 32, n0 = blockIdx.x * 32;
    int tx = threadIdx.x, ty = threadIdx.y;
    #pragma unroll
    for (int i = 0; i < 32; i += 8)
        t[ty + i][tx] = Wl[(size_t)(k0 + ty + i) * Ndim + n0 + tx];
    __syncthreads();
    #pragma unroll
    for (int i = 0; i < 32; i += 8) {
        int n = n0 + ty + i, k = k0 + tx;
        float v = t[tx][ty + i];
        __nv_bfloat16 hv = __float2bfloat16(v);
        hil[(size_t)n * Kdim + k] = hv;
        lol[(size_t)n * Kdim + k] = __float2bfloat16(v - __bfloat162float(hv));
    }
}

// ================= embed + PE (fp32 + hi/lo) =================
__global__ __launch_bounds__(256) void embed_kernel(const int* __restrict__ tokens,
                                                    const float* __restrict__ emb,
                                                    float* __restrict__ x,
                                                    __nv_bfloat16* __restrict__ xh,
                                                    __nv_bfloat16* __restrict__ xl) {
    int row = blockIdx.x;
    int s = row & (SS - 1);
    int tok = tokens[row];
    const float* e = emb + (size_t)tok * DD;
    int d0 = threadIdx.x * 4;
    float v[4];
    #pragma unroll
    for (int j = 0; j < 4; j++) {
        int d = d0 + j;
        int i2 = d & ~1;
        float denom = powf(10000.0f, (float)i2 / (float)DD);
        float ang = (float)s / denom;
        float pe = (d & 1) ? cosf(ang) : sinf(ang);
        v[j] = e[d] + pe;
    }
    size_t base = (size_t)row * DD + d0;
    *(float4*)(x + base) = make_float4(v[0], v[1], v[2], v[3]);
    store_hilo(xh, xl, base, v[0], v[1]);
    store_hilo(xh, xl, base + 2, v[2], v[3]);
}

// ================= residual + LayerNorm (fp32 out + hi/lo out) =================
__device__ __forceinline__ float warpReduceSum(float v) {
    #pragma unroll
    for (int o = 16; o; o >>= 1) v += __shfl_xor_sync(0xffffffffu, v, o);
    return v;
}
__device__ __forceinline__ float blockReduceSum(float v, float* sh) {
    v = warpReduceSum(v);
    int w = threadIdx.x >> 5;
    __syncthreads();
    if ((threadIdx.x & 31) == 0) sh[w] = v;
    __syncthreads();
    if (threadIdx.x < 32) {
        float t = (threadIdx.x < 8) ? sh[threadIdx.x] : 0.f;
        t = warpReduceSum(t);
        if (threadIdx.x == 0) sh[0] = t;
    }
    __syncthreads();
    return sh[0];
}

__global__ __launch_bounds__(256) void ln_kernel(const float* __restrict__ x,
                                                 const float* __restrict__ y,
                                                 const float* __restrict__ gamma,
                                                 const float* __restrict__ beta,
                                                 float* __restrict__ out,
                                                 __nv_bfloat16* __restrict__ oh,
                                                 __nv_bfloat16* __restrict__ ol) {
    __shared__ float sh[8];
    size_t row = blockIdx.x;
    int d0 = threadIdx.x * 4;
    float4 a = *(const float4*)(x + row * DD + d0);
    float4 b4 = *(const float4*)(y + row * DD + d0);
    float z[4] = { a.x + b4.x, a.y + b4.y, a.z + b4.z, a.w + b4.w };
    float ssum = z[0] + z[1] + z[2] + z[3];
    ssum = blockReduceSum(ssum, sh);
    float mean = ssum * (1.0f / DD);
    float d2 = 0.f;
    #pragma unroll
    for (int e = 0; e < 4; e++) { float u = z[e] - mean; d2 += u * u; }
    d2 = blockReduceSum(d2, sh);
    float inv = rsqrtf(d2 * (1.0f / DD) + EPSV);
    float4 g4 = *(const float4*)(gamma + d0);
    float4 be4 = *(const float4*)(beta + d0);
    float o0 = g4.x * ((z[0] - mean) * inv) + be4.x;
    float o1 = g4.y * ((z[1] - mean) * inv) + be4.y;
    float o2 = g4.z * ((z[2] - mean) * inv) + be4.z;
    float o3 = g4.w * ((z[3] - mean) * inv) + be4.w;
    size_t base = row * DD + d0;
    *(float4*)(out + base) = make_float4(o0, o1, o2, o3);
    store_hilo(oh, ol, base, o0, o1);
    store_hilo(oh, ol, base + 2, o2, o3);
}

// ================= orchestration =================
extern "C" void kernel_launch(void* const* d_in, const int* in_sizes, int n_in,
                              void* d_out, int out_size) {
    const int*   tokens = (const int*)d_in[0];
    const float* mask   = (const float*)d_in[1];
    const float* emb    = (const float*)d_in[2];
    const float* qkv_w  = (const float*)d_in[3];
    const float* qkv_b  = (const float*)d_in[4];
    const float* out_w  = (const float*)d_in[5];
    const float* out_b  = (const float*)d_in[6];
    const float* w1     = (const float*)d_in[7];
    const float* b1     = (const float*)d_in[8];
    const float* w2     = (const float*)d_in[9];
    const float* b2     = (const float*)d_in[10];
    const float* gamma  = (const float*)d_in[11];
    const float* beta   = (const float*)d_in[12];
    float* out = (float*)d_out;

    float *px, *py;
    cudaGetSymbolAddress((void**)&px, g_x);
    cudaGetSymbolAddress((void**)&py, g_y);
    __nv_bfloat16 *pahi, *palo, *pffh, *pffl, *pvoh, *pvol;
    __nv_bfloat16 *pqh, *pql, *poh, *pol, *p1h, *p1l, *p2h, *p2l;
    cudaGetSymbolAddress((void**)&pahi, g_ahi);
    cudaGetSymbolAddress((void**)&palo, g_alo);
    cudaGetSymbolAddress((void**)&pffh, g_ffh);
    cudaGetSymbolAddress((void**)&pffl, g_ffl);
    cudaGetSymbolAddress((void**)&pvoh, g_voh);
    cudaGetSymbolAddress((void**)&pvol, g_vol);
    cudaGetSymbolAddress((void**)&pqh,  g_wqkv_hi);
    cudaGetSymbolAddress((void**)&pql,  g_wqkv_lo);
    cudaGetSymbolAddress((void**)&poh,  g_wout_hi);
    cudaGetSymbolAddress((void**)&pol,  g_wout_lo);
    cudaGetSymbolAddress((void**)&p1h,  g_w1_hi);
    cudaGetSymbolAddress((void**)&p1l,  g_w1_lo);
    cudaGetSymbolAddress((void**)&p2h,  g_w2_hi);
    cudaGetSymbolAddress((void**)&p2l,  g_w2_lo);

    cudaFuncSetAttribute(gemm_mma<0>, cudaFuncAttributeMaxDynamicSharedMemorySize, GT_SMEM);
    cudaFuncSetAttribute(gemm_mma<1>, cudaFuncAttributeMaxDynamicSharedMemorySize, GT_SMEM);
    cudaFuncSetAttribute(gemm_mma<2>, cudaFuncAttributeMaxDynamicSharedMemorySize, GT_SMEM);
    cudaFuncSetAttribute(flash_attn, cudaFuncAttributeMaxDynamicSharedMemorySize, FA_SMEM);

    wsplit_t<<<dim3(3 * DD / 32, DD / 32, LL), dim3(32, 8)>>>(qkv_w, pqh, pql, DD, 3 * DD);
    wsplit_t<<<dim3(DD / 32, DD / 32, LL),     dim3(32, 8)>>>(out_w, poh, pol, DD, DD);
    wsplit_t<<<dim3(FF / 32, DD / 32, LL),     dim3(32, 8)>>>(w1, p1h, p1l, DD, FF);
    wsplit_t<<<dim3(DD / 32, FF / 32, LL),     dim3(32, 8)>>>(w2, p2h, p2l, FF, DD);

    embed_kernel<<<MM, 256>>>(tokens, emb, px, pahi, palo);

    for (int i = 0; i < LL; i++) {
        size_t l = (size_t)i;
        // QKV (scatter epilogue, q pre-scaled by 1/8)
        gemm_mma<2><<<dim3(3 * DD / GBN, MM / GBM), 256, GT_SMEM>>>(
            pahi, palo, pqh + l * 3 * DD * DD, pql + l * 3 * DD * DD,
            qkv_b + l * 3 * DD, nullptr, nullptr, nullptr, 3 * DD, DD);
        // fused attention
        flash_attn<<<dim3(SS / 128, BB * HH), 256, FA_SMEM>>>(mask);
        // out projection -> fp32
        gemm_mma<0><<<dim3(DD / GBN, MM / GBM), 256, GT_SMEM>>>(
            pvoh, pvol, poh + l * DD * DD, pol + l * DD * DD,
            out_b + l * DD, py, nullptr, nullptr, DD, DD);
        ln_kernel<<<MM, 256>>>(px, py, gamma + l * DD, beta + l * DD, px, pahi, palo);
        // FFN up (+ReLU) -> bf16 hi/lo
        gemm_mma<1><<<dim3(FF / GBN, MM / GBM), 256, GT_SMEM>>>(
            pahi, palo, p1h + l * DD * FF, p1l + l * DD * FF,
            b1 + l * FF, nullptr, pffh, pffl, FF, DD);
        // FFN down -> fp32
        gemm_mma<0><<<dim3(DD / GBN, MM / GBM), 256, GT_SMEM>>>(
            pffh, pffl, p2h + l * FF * DD, p2l + l * FF * DD,
            b2 + l * DD, py, nullptr, nullptr, DD, FF);
        ln_kernel<<<MM, 256>>>(px, py, gamma + l * DD, beta + l * DD,
                               (i == LL - 1) ? out : px, pahi, palo);
    }
}

// round 5
// speedup vs baseline: 3.1078x; 1.3528x over previous
#include <cuda_runtime.h>
#include <cuda_fp16.h>
#include <math.h>
#include <stdint.h>

#define BB 4
#define SS 1024
#define DD 1024
#define HH 16
#define HDIM 64
#define FF 4096
#define LL 6
#define MM (BB*SS)
#define EPSV 1e-5f

// ---------------- scratch (device globals; no allocation allowed) ----------------
__device__ float g_x[MM*DD];
__device__ float g_y[MM*DD];
__device__ __half g_a[MM*DD];          // fp16 activations (GEMM A input)
__device__ __half g_ffa[MM*FF];        // fp16 ffn hidden
__device__ __half g_q[BB*HH*SS*HDIM];  // q single (pre-scaled 1/8)
__device__ __half g_kh[BB*HH*SS*HDIM]; // k hi
__device__ __half g_kl[BB*HH*SS*HDIM]; // k lo
__device__ __half g_v[BB*HH*SS*HDIM];  // v single
__device__ __half g_vo[MM*DD];         // attention output single
// weights fp16 hi/lo, [N,K] K-major
__device__ __half g_wqkv_hi[(size_t)LL*3*DD*DD];
__device__ __half g_wqkv_lo[(size_t)LL*3*DD*DD];
__device__ __half g_wout_hi[(size_t)LL*DD*DD];
__device__ __half g_wout_lo[(size_t)LL*DD*DD];
__device__ __half g_w1_hi[(size_t)LL*DD*FF];
__device__ __half g_w1_lo[(size_t)LL*DD*FF];
__device__ __half g_w2_hi[(size_t)LL*FF*DD];
__device__ __half g_w2_lo[(size_t)LL*FF*DD];

// ================= PTX building blocks =================
__device__ __forceinline__ uint32_t smem_u32(const void* p) {
    return (uint32_t)__cvta_generic_to_shared((void*)p);
}
__device__ __forceinline__ void ldsm_x4(uint32_t (&r)[4], uint32_t addr) {
    asm volatile("ldmatrix.sync.aligned.m8n8.x4.shared.b16 {%0,%1,%2,%3}, [%4];"
        : "=r"(r[0]), "=r"(r[1]), "=r"(r[2]), "=r"(r[3]) : "r"(addr));
}
__device__ __forceinline__ void ldsm_x4_t(uint32_t (&r)[4], uint32_t addr) {
    asm volatile("ldmatrix.sync.aligned.m8n8.x4.trans.shared.b16 {%0,%1,%2,%3}, [%4];"
        : "=r"(r[0]), "=r"(r[1]), "=r"(r[2]), "=r"(r[3]) : "r"(addr));
}
__device__ __forceinline__ void ldsm_x2(uint32_t (&r)[2], uint32_t addr) {
    asm volatile("ldmatrix.sync.aligned.m8n8.x2.shared.b16 {%0,%1}, [%2];"
        : "=r"(r[0]), "=r"(r[1]) : "r"(addr));
}
__device__ __forceinline__ void mma16816(float (&d)[4], const uint32_t (&a)[4],
                                         const uint32_t (&b)[2]) {
    asm volatile(
        "mma.sync.aligned.m16n8k16.row.col.f32.f16.f16.f32 "
        "{%0,%1,%2,%3}, {%4,%5,%6,%7}, {%8,%9}, {%0,%1,%2,%3};"
        : "+f"(d[0]), "+f"(d[1]), "+f"(d[2]), "+f"(d[3])
        : "r"(a[0]), "r"(a[1]), "r"(a[2]), "r"(a[3]), "r"(b[0]), "r"(b[1]));
}
__device__ __forceinline__ void mma16816b(float (&d)[4], const uint32_t (&a)[4],
                                          uint32_t b0, uint32_t b1) {
    asm volatile(
        "mma.sync.aligned.m16n8k16.row.col.f32.f16.f16.f32 "
        "{%0,%1,%2,%3}, {%4,%5,%6,%7}, {%8,%9}, {%0,%1,%2,%3};"
        : "+f"(d[0]), "+f"(d[1]), "+f"(d[2]), "+f"(d[3])
        : "r"(a[0]), "r"(a[1]), "r"(a[2]), "r"(a[3]), "r"(b0), "r"(b1));
}
__device__ __forceinline__ void cp16(uint32_t dst, const void* src) {
    asm volatile("cp.async.cg.shared.global [%0], [%1], 16;" :: "r"(dst), "l"(src));
}
#define CP_COMMIT() asm volatile("cp.async.commit_group;" ::: "memory")
#define CP_WAIT1()  asm volatile("cp.async.wait_group 1;" ::: "memory")
#define CP_WAIT0()  asm volatile("cp.async.wait_group 0;" ::: "memory")

__device__ __forceinline__ void store_h2(__half* p, size_t idx, float a, float b) {
    *(__half2*)(p + idx) = __floats2half2_rn(a, b);
}
__device__ __forceinline__ void store_hilo(__half* ph, __half* pl, size_t idx,
                                           float a, float b) {
    __half ha = __float2half_rn(a), hb = __float2half_rn(b);
    *(__half2*)(ph + idx) = __half2(ha, hb);
    *(__half2*)(pl + idx) = __floats2half2_rn(a - __half2float(ha),
                                              b - __half2float(hb));
}
__device__ __forceinline__ uint32_t pack2h(float a, float b) {
    __half2 h = __floats2half2_rn(a, b);
    return *(uint32_t*)&h;
}

// ================= tensor-core GEMM (fp16 2-term) =================
// C[M,N] = A[M,K] @ W[K,N]; A fp16 single, W fp16 hi/lo [N,K] K-major.
// EPI: 0 = fp32 C; 1 = ReLU + fp16 single; 2 = QKV scatter.
#define GBM 128
#define GBN 128
#define GBK 32
#define ROWB 80
#define TILEB (128*ROWB)
#define STAGEB (3*TILEB)
#define GT_SMEM (2*STAGEB)

template<int EPI>
__global__ __launch_bounds__(256, 1) void gemm_mma(
    const __half* __restrict__ A,
    const __half* __restrict__ Bhi, const __half* __restrict__ Blo,
    const float* __restrict__ bias, float* __restrict__ Cf,
    __half* __restrict__ Ch, int N, int K)
{
    extern __shared__ char sm[];
    uint32_t sb = smem_u32(sm);
    int tid = threadIdx.x;
    int warp = tid >> 5, lane = tid & 31;
    int wm = warp >> 2, wn = warp & 3;
    int m0 = blockIdx.y * GBM, n0 = blockIdx.x * GBN;

    float acc[4][4][4];
    #pragma unroll
    for (int i = 0; i < 4; i++)
        #pragma unroll
        for (int j = 0; j < 4; j++)
            #pragma unroll
            for (int e = 0; e < 4; e++) acc[i][j][e] = 0.f;

    auto load_stage = [&](int s, int k0) {
        uint32_t base = sb + s * STAGEB;
        #pragma unroll
        for (int j = 0; j < 6; j++) {
            int ch = tid + 256 * j;
            int tile = ch >> 9, r = (ch >> 2) & 127, c = ch & 3;
            const __half* src = (tile == 0) ? A + (size_t)(m0 + r) * K + k0 + c * 8
                              : (tile == 1) ? Bhi + (size_t)(n0 + r) * K + k0 + c * 8
                                            : Blo + (size_t)(n0 + r) * K + k0 + c * 8;
            cp16(base + tile * TILEB + r * ROWB + c * 16, src);
        }
    };

    int T = K / GBK;
    load_stage(0, 0);
    CP_COMMIT();

    int a_r = lane & 15, a_c8 = (lane >> 4) * 8;
    int b_r = lane & 7,  b_c8 = ((lane >> 3) & 1) * 8;

    for (int t = 0; t < T; t++) {
        if (t + 1 < T) {
            load_stage((t + 1) & 1, (t + 1) * GBK);
            CP_COMMIT();
            CP_WAIT1();
        } else {
            CP_WAIT0();
        }
        __syncthreads();

        uint32_t base = sb + (t & 1) * STAGEB;
        #pragma unroll
        for (int kk = 0; kk < 2; kk++) {
            uint32_t af[4][4], bh[4][2], bl[4][2];
            #pragma unroll
            for (int mi = 0; mi < 4; mi++) {
                int row = wm * 64 + mi * 16 + a_r;
                ldsm_x4(af[mi], base + row * ROWB + (kk * 16 + a_c8) * 2);
            }
            #pragma unroll
            for (int ni = 0; ni < 4; ni++) {
                int row = wn * 32 + ni * 8 + b_r;
                uint32_t bd = base + TILEB + row * ROWB + (kk * 16 + b_c8) * 2;
                ldsm_x2(bh[ni], bd);
                ldsm_x2(bl[ni], bd + TILEB);
            }
            #pragma unroll
            for (int mi = 0; mi < 4; mi++)
                #pragma unroll
                for (int ni = 0; ni < 4; ni++) {
                    mma16816(acc[mi][ni], af[mi], bh[ni]);
                    mma16816(acc[mi][ni], af[mi], bl[ni]);
                }
        }
        __syncthreads();
    }

    int qr = lane >> 2, qc = (lane & 3) * 2;
    #pragma unroll
    for (int mi = 0; mi < 4; mi++) {
        #pragma unroll
        for (int ni = 0; ni < 4; ni++) {
            int gr = m0 + wm * 64 + mi * 16 + qr;
            int gc = n0 + wn * 32 + ni * 8 + qc;
            float b0 = bias[gc], b1 = bias[gc + 1];
            float v00 = acc[mi][ni][0] + b0, v01 = acc[mi][ni][1] + b1;
            float v10 = acc[mi][ni][2] + b0, v11 = acc[mi][ni][3] + b1;
            if (EPI == 0) {
                *(float2*)(Cf + (size_t)gr * N + gc)       = make_float2(v00, v01);
                *(float2*)(Cf + (size_t)(gr + 8) * N + gc) = make_float2(v10, v11);
            } else if (EPI == 1) {
                v00 = fmaxf(v00, 0.f); v01 = fmaxf(v01, 0.f);
                v10 = fmaxf(v10, 0.f); v11 = fmaxf(v11, 0.f);
                store_h2(Ch, (size_t)gr * N + gc,       v00, v01);
                store_h2(Ch, (size_t)(gr + 8) * N + gc, v10, v11);
            } else {
                int hh = gc / 192, inner = gc - hh * 192;
                int ty = inner >> 6, d = inner & 63;
                int bb = gr >> 10, si = gr & 1023;
                size_t dst = ((size_t)(bb * HH + hh) * SS + si) * HDIM + d;
                if (ty == 0) {
                    store_h2(g_q, dst,            v00 * 0.125f, v01 * 0.125f);
                    store_h2(g_q, dst + 8 * HDIM, v10 * 0.125f, v11 * 0.125f);
                } else if (ty == 1) {
                    store_hilo(g_kh, g_kl, dst,            v00, v01);
                    store_hilo(g_kh, g_kl, dst + 8 * HDIM, v10, v11);
                } else {
                    store_h2(g_v, dst,            v00, v01);
                    store_h2(g_v, dst + 8 * HDIM, v10, v11);
                }
            }
        }
    }
}

// ================= flash attention (fp16: Q single, K split, V single) ===========
#define FA_ROWF 144
#define FA_TILE (128*FA_ROWF)
#define FA_STAGE (3*FA_TILE)
#define FA_SMEM (2*FA_STAGE)

__global__ __launch_bounds__(256, 1) void flash_attn(const float* __restrict__ mask)
{
    extern __shared__ char sm[];
    uint32_t sb = smem_u32(sm);
    int tid = threadIdx.x, lane = tid & 31, w = tid >> 5;
    int qt = blockIdx.x, bh = blockIdx.y;
    int b = bh >> 4, h = bh & 15;
    size_t head = (size_t)bh * SS * HDIM;

    // ---- stage Q (single tile at sb) ----
    #pragma unroll
    for (int j = 0; j < 4; j++) {
        int ch = tid + 256 * j;
        int row = (ch >> 3) & 127, c = ch & 7;
        cp16(sb + row * FA_ROWF + c * 16,
             g_q + head + (size_t)(qt * 128 + row) * HDIM + c * 8);
    }
    CP_COMMIT(); CP_WAIT0();
    __syncthreads();

    uint32_t qf[4][4];
    {
        int ar = lane & 15, ac = (lane >> 4) * 8;
        #pragma unroll
        for (int kb = 0; kb < 4; kb++)
            ldsm_x4(qf[kb], sb + (w * 16 + ar) * FA_ROWF + (kb * 16 + ac) * 2);
    }
    __syncthreads();

    auto load_kv = [&](int s, int kt) {
        uint32_t base = sb + s * FA_STAGE;
        size_t goff = head + (size_t)(kt * 128) * HDIM;
        #pragma unroll
        for (int j = 0; j < 12; j++) {
            int ch = tid + 256 * j;
            int tile = ch >> 10, row = (ch >> 3) & 127, c = ch & 7;
            const __half* sp = (tile == 0) ? g_kh : (tile == 1) ? g_kl : g_v;
            cp16(base + tile * FA_TILE + row * FA_ROWF + c * 16,
                 sp + goff + (size_t)row * HDIM + c * 8);
        }
    };
    load_kv(0, 0);
    CP_COMMIT();

    int g = lane >> 2, t = lane & 3;
    int krow = (lane & 7) + ((lane >> 4) & 1) * 8, kcol = ((lane >> 3) & 1) * 8;
    int vrow = (lane & 7) + ((lane >> 3) & 1) * 8, vcol = ((lane >> 4) & 1) * 8;
    int qrow0 = qt * 128 + w * 16 + g;
    const float* mrow0 = mask + ((size_t)(b * SS + qrow0)) * SS;

    float m0v = -1e30f, m1v = -1e30f, l0v = 0.f, l1v = 0.f;
    float o[8][4];
    #pragma unroll
    for (int nf = 0; nf < 8; nf++)
        #pragma unroll
        for (int e = 0; e < 4; e++) o[nf][e] = 0.f;

    for (int kt = 0; kt < 8; kt++) {
        if (kt < 7) { load_kv((kt + 1) & 1, kt + 1); CP_COMMIT(); CP_WAIT1(); }
        else CP_WAIT0();
        __syncthreads();
        uint32_t base = sb + (kt & 1) * FA_STAGE;

        // ---- S = Q K^T (Q single, K hi+lo) ----
        float s[16][4];
        #pragma unroll
        for (int np = 0; np < 8; np++) {
            #pragma unroll
            for (int e = 0; e < 4; e++) { s[2*np][e] = 0.f; s[2*np+1][e] = 0.f; }
            #pragma unroll
            for (int kb = 0; kb < 4; kb++) {
                uint32_t ka = base + (np * 16 + krow) * FA_ROWF + (kb * 16 + kcol) * 2;
                uint32_t kh4[4], kl4[4];
                ldsm_x4(kh4, ka);
                ldsm_x4(kl4, ka + FA_TILE);
                mma16816b(s[2*np],   qf[kb], kh4[0], kh4[1]);
                mma16816b(s[2*np+1], qf[kb], kh4[2], kh4[3]);
                mma16816b(s[2*np],   qf[kb], kl4[0], kl4[1]);
                mma16816b(s[2*np+1], qf[kb], kl4[2], kl4[3]);
            }
        }

        // ---- mask + online softmax ----
        float mx0 = -1e30f, mx1 = -1e30f;
        #pragma unroll
        for (int ni = 0; ni < 16; ni++) {
            const float* mp = mrow0 + kt * 128 + ni * 8 + 2 * t;
            float2 mk0 = *(const float2*)mp;
            float2 mk1 = *(const float2*)(mp + 8 * SS);
            s[ni][0] += mk0.x; s[ni][1] += mk0.y;
            s[ni][2] += mk1.x; s[ni][3] += mk1.y;
            mx0 = fmaxf(mx0, fmaxf(s[ni][0], s[ni][1]));
            mx1 = fmaxf(mx1, fmaxf(s[ni][2], s[ni][3]));
        }
        mx0 = fmaxf(mx0, __shfl_xor_sync(0xffffffffu, mx0, 1));
        mx0 = fmaxf(mx0, __shfl_xor_sync(0xffffffffu, mx0, 2));
        mx1 = fmaxf(mx1, __shfl_xor_sync(0xffffffffu, mx1, 1));
        mx1 = fmaxf(mx1, __shfl_xor_sync(0xffffffffu, mx1, 2));
        float mn0 = fmaxf(m0v, mx0), mn1 = fmaxf(m1v, mx1);
        float a0 = __expf(m0v - mn0), a1 = __expf(m1v - mn1);
        m0v = mn0; m1v = mn1;
        l0v *= a0; l1v *= a1;
        #pragma unroll
        for (int nf = 0; nf < 8; nf++) {
            o[nf][0] *= a0; o[nf][1] *= a0; o[nf][2] *= a1; o[nf][3] *= a1;
        }
        #pragma unroll
        for (int ni = 0; ni < 16; ni++) {
            s[ni][0] = __expf(s[ni][0] - mn0); s[ni][1] = __expf(s[ni][1] - mn0);
            s[ni][2] = __expf(s[ni][2] - mn1); s[ni][3] = __expf(s[ni][3] - mn1);
            l0v += s[ni][0] + s[ni][1];
            l1v += s[ni][2] + s[ni][3];
        }

        // ---- O += P V (P single fp16, V single via ldmatrix.trans) ----
        #pragma unroll
        for (int ks = 0; ks < 8; ks++) {
            uint32_t pa[4];
            pa[0] = pack2h(s[2*ks][0],   s[2*ks][1]);
            pa[1] = pack2h(s[2*ks][2],   s[2*ks][3]);
            pa[2] = pack2h(s[2*ks+1][0], s[2*ks+1][1]);
            pa[3] = pack2h(s[2*ks+1][2], s[2*ks+1][3]);
            #pragma unroll
            for (int nv = 0; nv < 4; nv++) {
                uint32_t va = base + 2*FA_TILE + (ks * 16 + vrow) * FA_ROWF
                              + (nv * 16 + vcol) * 2;
                uint32_t v4[4];
                ldsm_x4_t(v4, va);
                mma16816b(o[2*nv],   pa, v4[0], v4[1]);
                mma16816b(o[2*nv+1], pa, v4[2], v4[3]);
            }
        }
        __syncthreads();
    }

    // ---- finalize ----
    l0v += __shfl_xor_sync(0xffffffffu, l0v, 1);
    l0v += __shfl_xor_sync(0xffffffffu, l0v, 2);
    l1v += __shfl_xor_sync(0xffffffffu, l1v, 1);
    l1v += __shfl_xor_sync(0xffffffffu, l1v, 2);
    float inv0 = 1.f / l0v, inv1 = 1.f / l1v;
    size_t orow0 = (size_t)(b * SS + qrow0) * DD + h * HDIM;
    size_t orow1 = orow0 + (size_t)8 * DD;
    #pragma unroll
    for (int nf = 0; nf < 8; nf++) {
        int col = nf * 8 + 2 * t;
        store_h2(g_vo, orow0 + col, o[nf][0] * inv0, o[nf][1] * inv0);
        store_h2(g_vo, orow1 + col, o[nf][2] * inv1, o[nf][3] * inv1);
    }
}

// ================= weight transpose+split (fp16) =================
__global__ __launch_bounds__(256) void wsplit_t(const float* __restrict__ W,
                                                __half* __restrict__ hi,
                                                __half* __restrict__ lo,
                                                int Kdim, int Ndim) {
    __shared__ float t[32][33];
    size_t loff = (size_t)blockIdx.z * Kdim * Ndim;
    const float* Wl = W + loff;
    __half* hil = hi + loff;
    __half* lol = lo + loff;
    int k0 = blockIdx.y * 32, n0 = blockIdx.x * 32;
    int tx = threadIdx.x, ty = threadIdx.y;
    #pragma unroll
    for (int i = 0; i < 32; i += 8)
        t[ty + i][tx] = Wl[(size_t)(k0 + ty + i) * Ndim + n0 + tx];
    __syncthreads();
    #pragma unroll
    for (int i = 0; i < 32; i += 8) {
        int n = n0 + ty + i, k = k0 + tx;
        float v = t[tx][ty + i];
        __half hv = __float2half_rn(v);
        hil[(size_t)n * Kdim + k] = hv;
        lol[(size_t)n * Kdim + k] = __float2half_rn(v - __half2float(hv));
    }
}

// ================= embed + PE =================
__global__ __launch_bounds__(256) void embed_kernel(const int* __restrict__ tokens,
                                                    const float* __restrict__ emb,
                                                    float* __restrict__ x,
                                                    __half* __restrict__ xh) {
    int row = blockIdx.x;
    int s = row & (SS - 1);
    int tok = tokens[row];
    const float* e = emb + (size_t)tok * DD;
    int d0 = threadIdx.x * 4;
    float v[4];
    #pragma unroll
    for (int j = 0; j < 4; j++) {
        int d = d0 + j;
        int i2 = d & ~1;
        float denom = powf(10000.0f, (float)i2 / (float)DD);
        float ang = (float)s / denom;
        float pe = (d & 1) ? cosf(ang) : sinf(ang);
        v[j] = e[d] + pe;
    }
    size_t base = (size_t)row * DD + d0;
    *(float4*)(x + base) = make_float4(v[0], v[1], v[2], v[3]);
    store_h2(xh, base, v[0], v[1]);
    store_h2(xh, base + 2, v[2], v[3]);
}

// ================= residual + LayerNorm =================
__device__ __forceinline__ float warpReduceSum(float v) {
    #pragma unroll
    for (int o = 16; o; o >>= 1) v += __shfl_xor_sync(0xffffffffu, v, o);
    return v;
}
__device__ __forceinline__ float blockReduceSum(float v, float* sh) {
    v = warpReduceSum(v);
    int w = threadIdx.x >> 5;
    __syncthreads();
    if ((threadIdx.x & 31) == 0) sh[w] = v;
    __syncthreads();
    if (threadIdx.x < 32) {
        float t = (threadIdx.x < 8) ? sh[threadIdx.x] : 0.f;
        t = warpReduceSum(t);
        if (threadIdx.x == 0) sh[0] = t;
    }
    __syncthreads();
    return sh[0];
}

__global__ __launch_bounds__(256) void ln_kernel(const float* __restrict__ x,
                                                 const float* __restrict__ y,
                                                 const float* __restrict__ gamma,
                                                 const float* __restrict__ beta,
                                                 float* __restrict__ out,
                                                 __half* __restrict__ oh) {
    __shared__ float sh[8];
    size_t row = blockIdx.x;
    int d0 = threadIdx.x * 4;
    float4 a = *(const float4*)(x + row * DD + d0);
    float4 b4 = *(const float4*)(y + row * DD + d0);
    float z[4] = { a.x + b4.x, a.y + b4.y, a.z + b4.z, a.w + b4.w };
    float ssum = z[0] + z[1] + z[2] + z[3];
    ssum = blockReduceSum(ssum, sh);
    float mean = ssum * (1.0f / DD);
    float d2 = 0.f;
    #pragma unroll
    for (int e = 0; e < 4; e++) { float u = z[e] - mean; d2 += u * u; }
    d2 = blockReduceSum(d2, sh);
    float inv = rsqrtf(d2 * (1.0f / DD) + EPSV);
    float4 g4 = *(const float4*)(gamma + d0);
    float4 be4 = *(const float4*)(beta + d0);
    float o0 = g4.x * ((z[0] - mean) * inv) + be4.x;
    float o1 = g4.y * ((z[1] - mean) * inv) + be4.y;
    float o2 = g4.z * ((z[2] - mean) * inv) + be4.z;
    float o3 = g4.w * ((z[3] - mean) * inv) + be4.w;
    size_t base = row * DD + d0;
    *(float4*)(out + base) = make_float4(o0, o1, o2, o3);
    store_h2(oh, base, o0, o1);
    store_h2(oh, base + 2, o2, o3);
}

// ================= orchestration =================
extern "C" void kernel_launch(void* const* d_in, const int* in_sizes, int n_in,
                              void* d_out, int out_size) {
    const int*   tokens = (const int*)d_in[0];
    const float* mask   = (const float*)d_in[1];
    const float* emb    = (const float*)d_in[2];
    const float* qkv_w  = (const float*)d_in[3];
    const float* qkv_b  = (const float*)d_in[4];
    const float* out_w  = (const float*)d_in[5];
    const float* out_b  = (const float*)d_in[6];
    const float* w1     = (const float*)d_in[7];
    const float* b1     = (const float*)d_in[8];
    const float* w2     = (const float*)d_in[9];
    const float* b2     = (const float*)d_in[10];
    const float* gamma  = (const float*)d_in[11];
    const float* beta   = (const float*)d_in[12];
    float* out = (float*)d_out;

    float *px, *py;
    cudaGetSymbolAddress((void**)&px, g_x);
    cudaGetSymbolAddress((void**)&py, g_y);
    __half *pa, *pffa, *pvo;
    __half *pqh, *pql, *poh, *pol, *p1h, *p1l, *p2h, *p2l;
    cudaGetSymbolAddress((void**)&pa,   g_a);
    cudaGetSymbolAddress((void**)&pffa, g_ffa);
    cudaGetSymbolAddress((void**)&pvo,  g_vo);
    cudaGetSymbolAddress((void**)&pqh,  g_wqkv_hi);
    cudaGetSymbolAddress((void**)&pql,  g_wqkv_lo);
    cudaGetSymbolAddress((void**)&poh,  g_wout_hi);
    cudaGetSymbolAddress((void**)&pol,  g_wout_lo);
    cudaGetSymbolAddress((void**)&p1h,  g_w1_hi);
    cudaGetSymbolAddress((void**)&p1l,  g_w1_lo);
    cudaGetSymbolAddress((void**)&p2h,  g_w2_hi);
    cudaGetSymbolAddress((void**)&p2l,  g_w2_lo);

    cudaFuncSetAttribute(gemm_mma<0>, cudaFuncAttributeMaxDynamicSharedMemorySize, GT_SMEM);
    cudaFuncSetAttribute(gemm_mma<1>, cudaFuncAttributeMaxDynamicSharedMemorySize, GT_SMEM);
    cudaFuncSetAttribute(gemm_mma<2>, cudaFuncAttributeMaxDynamicSharedMemorySize, GT_SMEM);
    cudaFuncSetAttribute(flash_attn, cudaFuncAttributeMaxDynamicSharedMemorySize, FA_SMEM);

    wsplit_t<<<dim3(3 * DD / 32, DD / 32, LL), dim3(32, 8)>>>(qkv_w, pqh, pql, DD, 3 * DD);
    wsplit_t<<<dim3(DD / 32, DD / 32, LL),     dim3(32, 8)>>>(out_w, poh, pol, DD, DD);
    wsplit_t<<<dim3(FF / 32, DD / 32, LL),     dim3(32, 8)>>>(w1, p1h, p1l, DD, FF);
    wsplit_t<<<dim3(DD / 32, FF / 32, LL),     dim3(32, 8)>>>(w2, p2h, p2l, FF, DD);

    embed_kernel<<<MM, 256>>>(tokens, emb, px, pa);

    for (int i = 0; i < LL; i++) {
        size_t l = (size_t)i;
        // QKV (scatter epilogue)
        gemm_mma<2><<<dim3(3 * DD / GBN, MM / GBM), 256, GT_SMEM>>>(
            pa, pqh + l * 3 * DD * DD, pql + l * 3 * DD * DD,
            qkv_b + l * 3 * DD, nullptr, nullptr, 3 * DD, DD);
        // fused attention
        flash_attn<<<dim3(SS / 128, BB * HH), 256, FA_SMEM>>>(mask);
        // out projection -> fp32
        gemm_mma<0><<<dim3(DD / GBN, MM / GBM), 256, GT_SMEM>>>(
            pvo, poh + l * DD * DD, pol + l * DD * DD,
            out_b + l * DD, py, nullptr, DD, DD);
        ln_kernel<<<MM, 256>>>(px, py, gamma + l * DD, beta + l * DD, px, pa);
        // FFN up (+ReLU) -> fp16
        gemm_mma<1><<<dim3(FF / GBN, MM / GBM), 256, GT_SMEM>>>(
            pa, p1h + l * DD * FF, p1l + l * DD * FF,
            b1 + l * FF, nullptr, pffa, FF, DD);
        // FFN down -> fp32
        gemm_mma<0><<<dim3(DD / GBN, MM / GBM), 256, GT_SMEM>>>(
            pffa, p2h + l * FF * DD, p2l + l * FF * DD,
            b2 + l * DD, py, nullptr, DD, FF);
        ln_kernel<<<MM, 256>>>(px, py, gamma + l * DD, beta + l * DD,
                               (i == LL - 1) ? out : px, pa);
    }
}

// round 6
// speedup vs baseline: 3.1258x; 1.0058x over previous
#include <cuda_runtime.h>
#include <cuda_fp16.h>
#include <math.h>
#include <stdint.h>

#define BB 4
#define SS 1024
#define DD 1024
#define HH 16
#define HDIM 64
#define FF 4096
#define LL 6
#define MM (BB*SS)
#define EPSV 1e-5f

// ---------------- scratch (device globals; no allocation allowed) ----------------
__device__ float g_x[MM*DD];
__device__ float g_y[MM*DD];
__device__ __half g_a[MM*DD];
__device__ __half g_ffa[MM*FF];
__device__ __half g_q[BB*HH*SS*HDIM];
__device__ __half g_kh[BB*HH*SS*HDIM];
__device__ __half g_kl[BB*HH*SS*HDIM];
__device__ __half g_v[BB*HH*SS*HDIM];
__device__ __half g_vo[MM*DD];
__device__ __half g_wqkv_hi[(size_t)LL*3*DD*DD];
__device__ __half g_wqkv_lo[(size_t)LL*3*DD*DD];
__device__ __half g_wout_hi[(size_t)LL*DD*DD];
__device__ __half g_wout_lo[(size_t)LL*DD*DD];
__device__ __half g_w1_hi[(size_t)LL*DD*FF];
__device__ __half g_w1_lo[(size_t)LL*DD*FF];
__device__ __half g_w2_hi[(size_t)LL*FF*DD];
__device__ __half g_w2_lo[(size_t)LL*FF*DD];

// ================= PTX building blocks =================
__device__ __forceinline__ uint32_t smem_u32(const void* p) {
    return (uint32_t)__cvta_generic_to_shared((void*)p);
}
__device__ __forceinline__ void ldsm_x4(uint32_t (&r)[4], uint32_t addr) {
    asm volatile("ldmatrix.sync.aligned.m8n8.x4.shared.b16 {%0,%1,%2,%3}, [%4];"
        : "=r"(r[0]), "=r"(r[1]), "=r"(r[2]), "=r"(r[3]) : "r"(addr));
}
__device__ __forceinline__ void ldsm_x4_t(uint32_t (&r)[4], uint32_t addr) {
    asm volatile("ldmatrix.sync.aligned.m8n8.x4.trans.shared.b16 {%0,%1,%2,%3}, [%4];"
        : "=r"(r[0]), "=r"(r[1]), "=r"(r[2]), "=r"(r[3]) : "r"(addr));
}
__device__ __forceinline__ void ldsm_x2(uint32_t (&r)[2], uint32_t addr) {
    asm volatile("ldmatrix.sync.aligned.m8n8.x2.shared.b16 {%0,%1}, [%2];"
        : "=r"(r[0]), "=r"(r[1]) : "r"(addr));
}
__device__ __forceinline__ void mma16816(float (&d)[4], const uint32_t (&a)[4],
                                         const uint32_t (&b)[2]) {
    asm volatile(
        "mma.sync.aligned.m16n8k16.row.col.f32.f16.f16.f32 "
        "{%0,%1,%2,%3}, {%4,%5,%6,%7}, {%8,%9}, {%0,%1,%2,%3};"
        : "+f"(d[0]), "+f"(d[1]), "+f"(d[2]), "+f"(d[3])
        : "r"(a[0]), "r"(a[1]), "r"(a[2]), "r"(a[3]), "r"(b[0]), "r"(b[1]));
}
__device__ __forceinline__ void mma16816b(float (&d)[4], const uint32_t (&a)[4],
                                          uint32_t b0, uint32_t b1) {
    asm volatile(
        "mma.sync.aligned.m16n8k16.row.col.f32.f16.f16.f32 "
        "{%0,%1,%2,%3}, {%4,%5,%6,%7}, {%8,%9}, {%0,%1,%2,%3};"
        : "+f"(d[0]), "+f"(d[1]), "+f"(d[2]), "+f"(d[3])
        : "r"(a[0]), "r"(a[1]), "r"(a[2]), "r"(a[3]), "r"(b0), "r"(b1));
}
__device__ __forceinline__ void cp16(uint32_t dst, const void* src) {
    asm volatile("cp.async.cg.shared.global [%0], [%1], 16;" :: "r"(dst), "l"(src));
}
#define CP_COMMIT() asm volatile("cp.async.commit_group;" ::: "memory")
#define CP_WAIT2()  asm volatile("cp.async.wait_group 2;" ::: "memory")
#define CP_WAIT1()  asm volatile("cp.async.wait_group 1;" ::: "memory")
#define CP_WAIT0()  asm volatile("cp.async.wait_group 0;" ::: "memory")

__device__ __forceinline__ void store_h2(__half* p, size_t idx, float a, float b) {
    *(__half2*)(p + idx) = __floats2half2_rn(a, b);
}
__device__ __forceinline__ void store_hilo(__half* ph, __half* pl, size_t idx,
                                           float a, float b) {
    __half ha = __float2half_rn(a), hb = __float2half_rn(b);
    *(__half2*)(ph + idx) = __half2(ha, hb);
    *(__half2*)(pl + idx) = __floats2half2_rn(a - __half2float(ha),
                                              b - __half2float(hb));
}
__device__ __forceinline__ uint32_t pack2h(float a, float b) {
    __half2 h = __floats2half2_rn(a, b);
    return *(uint32_t*)&h;
}

// ================= tensor-core GEMM (fp16 2-term, 4-stage pipeline) ==============
#define GBM 128
#define GBN 128
#define GBK 32
#define ROWB 80
#define TILEB (128*ROWB)
#define STAGEB (3*TILEB)
#define NSTG 4
#define GT_SMEM (NSTG*STAGEB)

template<int EPI>
__global__ __launch_bounds__(256, 1) void gemm_mma(
    const __half* __restrict__ A,
    const __half* __restrict__ Bhi, const __half* __restrict__ Blo,
    const float* __restrict__ bias, float* __restrict__ Cf,
    __half* __restrict__ Ch, int N, int K)
{
    extern __shared__ char sm[];
    uint32_t sb = smem_u32(sm);
    int tid = threadIdx.x;
    int warp = tid >> 5, lane = tid & 31;
    int wm = warp >> 2, wn = warp & 3;
    int m0 = blockIdx.y * GBM, n0 = blockIdx.x * GBN;

    float acc[4][4][4];
    #pragma unroll
    for (int i = 0; i < 4; i++)
        #pragma unroll
        for (int j = 0; j < 4; j++)
            #pragma unroll
            for (int e = 0; e < 4; e++) acc[i][j][e] = 0.f;

    auto load_stage = [&](int s, int k0) {
        uint32_t base = sb + s * STAGEB;
        #pragma unroll
        for (int j = 0; j < 6; j++) {
            int ch = tid + 256 * j;
            int tile = ch >> 9, r = (ch >> 2) & 127, c = ch & 3;
            const __half* src = (tile == 0) ? A + (size_t)(m0 + r) * K + k0 + c * 8
                              : (tile == 1) ? Bhi + (size_t)(n0 + r) * K + k0 + c * 8
                                            : Blo + (size_t)(n0 + r) * K + k0 + c * 8;
            cp16(base + tile * TILEB + r * ROWB + c * 16, src);
        }
    };

    int T = K / GBK;           // 32 or 128, always >= NSTG
    load_stage(0, 0);          CP_COMMIT();
    load_stage(1, GBK);        CP_COMMIT();
    load_stage(2, 2 * GBK);    CP_COMMIT();

    int a_r = lane & 15, a_c8 = (lane >> 4) * 8;
    int b_r = lane & 7,  b_c8 = ((lane >> 3) & 1) * 8;

    for (int t = 0; t < T; t++) {
        // ensure stage t complete (groups issued so far: 0..min(t+2, T-1))
        if (t + 2 < T)      { CP_WAIT2(); }
        else if (t + 1 < T) { CP_WAIT1(); }
        else                { CP_WAIT0(); }
        __syncthreads();     // all warps see stage t; all done reading stage (t-1)
        if (t + 3 < T) { load_stage((t + 3) & (NSTG - 1), (t + 3) * GBK); CP_COMMIT(); }

        uint32_t base = sb + (t & (NSTG - 1)) * STAGEB;
        #pragma unroll
        for (int kk = 0; kk < 2; kk++) {
            uint32_t af[4][4], bh[4][2], bl[4][2];
            #pragma unroll
            for (int mi = 0; mi < 4; mi++) {
                int row = wm * 64 + mi * 16 + a_r;
                ldsm_x4(af[mi], base + row * ROWB + (kk * 16 + a_c8) * 2);
            }
            #pragma unroll
            for (int ni = 0; ni < 4; ni++) {
                int row = wn * 32 + ni * 8 + b_r;
                uint32_t bd = base + TILEB + row * ROWB + (kk * 16 + b_c8) * 2;
                ldsm_x2(bh[ni], bd);
                ldsm_x2(bl[ni], bd + TILEB);
            }
            #pragma unroll
            for (int mi = 0; mi < 4; mi++)
                #pragma unroll
                for (int ni = 0; ni < 4; ni++) {
                    mma16816(acc[mi][ni], af[mi], bh[ni]);
                    mma16816(acc[mi][ni], af[mi], bl[ni]);
                }
        }
    }

    int qr = lane >> 2, qc = (lane & 3) * 2;
    #pragma unroll
    for (int mi = 0; mi < 4; mi++) {
        #pragma unroll
        for (int ni = 0; ni < 4; ni++) {
            int gr = m0 + wm * 64 + mi * 16 + qr;
            int gc = n0 + wn * 32 + ni * 8 + qc;
            float b0 = bias[gc], b1 = bias[gc + 1];
            float v00 = acc[mi][ni][0] + b0, v01 = acc[mi][ni][1] + b1;
            float v10 = acc[mi][ni][2] + b0, v11 = acc[mi][ni][3] + b1;
            if (EPI == 0) {
                *(float2*)(Cf + (size_t)gr * N + gc)       = make_float2(v00, v01);
                *(float2*)(Cf + (size_t)(gr + 8) * N + gc) = make_float2(v10, v11);
            } else if (EPI == 1) {
                v00 = fmaxf(v00, 0.f); v01 = fmaxf(v01, 0.f);
                v10 = fmaxf(v10, 0.f); v11 = fmaxf(v11, 0.f);
                store_h2(Ch, (size_t)gr * N + gc,       v00, v01);
                store_h2(Ch, (size_t)(gr + 8) * N + gc, v10, v11);
            } else {
                int hh = gc / 192, inner = gc - hh * 192;
                int ty = inner >> 6, d = inner & 63;
                int bb = gr >> 10, si = gr & 1023;
                size_t dst = ((size_t)(bb * HH + hh) * SS + si) * HDIM + d;
                if (ty == 0) {
                    store_h2(g_q, dst,            v00 * 0.125f, v01 * 0.125f);
                    store_h2(g_q, dst + 8 * HDIM, v10 * 0.125f, v11 * 0.125f);
                } else if (ty == 1) {
                    store_hilo(g_kh, g_kl, dst,            v00, v01);
                    store_hilo(g_kh, g_kl, dst + 8 * HDIM, v10, v11);
                } else {
                    store_h2(g_v, dst,            v00, v01);
                    store_h2(g_v, dst + 8 * HDIM, v10, v11);
                }
            }
        }
    }
}

// ================= flash attention (fp16, 3-stage KV pipeline) =================
#define FA_ROWF 144
#define FA_TILE (128*FA_ROWF)
#define FA_STAGE (3*FA_TILE)
#define FA_NSTG 3
#define FA_SMEM (FA_NSTG*FA_STAGE)

__global__ __launch_bounds__(256, 1) void flash_attn(const float* __restrict__ mask)
{
    extern __shared__ char sm[];
    uint32_t sb = smem_u32(sm);
    int tid = threadIdx.x, lane = tid & 31, w = tid >> 5;
    int qt = blockIdx.x, bh = blockIdx.y;
    int b = bh >> 4, h = bh & 15;
    size_t head = (size_t)bh * SS * HDIM;

    // ---- stage Q ----
    #pragma unroll
    for (int j = 0; j < 4; j++) {
        int ch = tid + 256 * j;
        int row = (ch >> 3) & 127, c = ch & 7;
        cp16(sb + row * FA_ROWF + c * 16,
             g_q + head + (size_t)(qt * 128 + row) * HDIM + c * 8);
    }
    CP_COMMIT(); CP_WAIT0();
    __syncthreads();

    uint32_t qf[4][4];
    {
        int ar = lane & 15, ac = (lane >> 4) * 8;
        #pragma unroll
        for (int kb = 0; kb < 4; kb++)
            ldsm_x4(qf[kb], sb + (w * 16 + ar) * FA_ROWF + (kb * 16 + ac) * 2);
    }
    __syncthreads();

    auto load_kv = [&](int s, int kt) {
        uint32_t base = sb + s * FA_STAGE;
        size_t goff = head + (size_t)(kt * 128) * HDIM;
        #pragma unroll
        for (int j = 0; j < 12; j++) {
            int ch = tid + 256 * j;
            int tile = ch >> 10, row = (ch >> 3) & 127, c = ch & 7;
            const __half* sp = (tile == 0) ? g_kh : (tile == 1) ? g_kl : g_v;
            cp16(base + tile * FA_TILE + row * FA_ROWF + c * 16,
                 sp + goff + (size_t)row * HDIM + c * 8);
        }
    };
    load_kv(0, 0); CP_COMMIT();
    load_kv(1, 1); CP_COMMIT();

    int g = lane >> 2, t = lane & 3;
    int krow = (lane & 7) + ((lane >> 4) & 1) * 8, kcol = ((lane >> 3) & 1) * 8;
    int vrow = (lane & 7) + ((lane >> 3) & 1) * 8, vcol = ((lane >> 4) & 1) * 8;
    int qrow0 = qt * 128 + w * 16 + g;
    const float* mrow0 = mask + ((size_t)(b * SS + qrow0)) * SS;

    float m0v = -1e30f, m1v = -1e30f, l0v = 0.f, l1v = 0.f;
    float o[8][4];
    #pragma unroll
    for (int nf = 0; nf < 8; nf++)
        #pragma unroll
        for (int e = 0; e < 4; e++) o[nf][e] = 0.f;

    const int T = 8;
    for (int kt = 0; kt < T; kt++) {
        if (kt < T - 1) { CP_WAIT1(); } else { CP_WAIT0(); }
        __syncthreads();
        if (kt + 2 < T) { load_kv((kt + 2) % FA_NSTG, kt + 2); CP_COMMIT(); }
        uint32_t base = sb + (kt % FA_NSTG) * FA_STAGE;

        // ---- S = Q K^T (Q single, K hi+lo) ----
        float s[16][4];
        #pragma unroll
        for (int np = 0; np < 8; np++) {
            #pragma unroll
            for (int e = 0; e < 4; e++) { s[2*np][e] = 0.f; s[2*np+1][e] = 0.f; }
            #pragma unroll
            for (int kb = 0; kb < 4; kb++) {
                uint32_t ka = base + (np * 16 + krow) * FA_ROWF + (kb * 16 + kcol) * 2;
                uint32_t kh4[4], kl4[4];
                ldsm_x4(kh4, ka);
                ldsm_x4(kl4, ka + FA_TILE);
                mma16816b(s[2*np],   qf[kb], kh4[0], kh4[1]);
                mma16816b(s[2*np+1], qf[kb], kh4[2], kh4[3]);
                mma16816b(s[2*np],   qf[kb], kl4[0], kl4[1]);
                mma16816b(s[2*np+1], qf[kb], kl4[2], kl4[3]);
            }
        }

        // ---- mask + online softmax ----
        float mx0 = -1e30f, mx1 = -1e30f;
        #pragma unroll
        for (int ni = 0; ni < 16; ni++) {
            const float* mp = mrow0 + kt * 128 + ni * 8 + 2 * t;
            float2 mk0 = *(const float2*)mp;
            float2 mk1 = *(const float2*)(mp + 8 * SS);
            s[ni][0] += mk0.x; s[ni][1] += mk0.y;
            s[ni][2] += mk1.x; s[ni][3] += mk1.y;
            mx0 = fmaxf(mx0, fmaxf(s[ni][0], s[ni][1]));
            mx1 = fmaxf(mx1, fmaxf(s[ni][2], s[ni][3]));
        }
        mx0 = fmaxf(mx0, __shfl_xor_sync(0xffffffffu, mx0, 1));
        mx0 = fmaxf(mx0, __shfl_xor_sync(0xffffffffu, mx0, 2));
        mx1 = fmaxf(mx1, __shfl_xor_sync(0xffffffffu, mx1, 1));
        mx1 = fmaxf(mx1, __shfl_xor_sync(0xffffffffu, mx1, 2));
        float mn0 = fmaxf(m0v, mx0), mn1 = fmaxf(m1v, mx1);
        float a0 = __expf(m0v - mn0), a1 = __expf(m1v - mn1);
        m0v = mn0; m1v = mn1;
        l0v *= a0; l1v *= a1;
        #pragma unroll
        for (int nf = 0; nf < 8; nf++) {
            o[nf][0] *= a0; o[nf][1] *= a0; o[nf][2] *= a1; o[nf][3] *= a1;
        }
        #pragma unroll
        for (int ni = 0; ni < 16; ni++) {
            s[ni][0] = __expf(s[ni][0] - mn0); s[ni][1] = __expf(s[ni][1] - mn0);
            s[ni][2] = __expf(s[ni][2] - mn1); s[ni][3] = __expf(s[ni][3] - mn1);
            l0v += s[ni][0] + s[ni][1];
            l1v += s[ni][2] + s[ni][3];
        }

        // ---- O += P V ----
        #pragma unroll
        for (int ks = 0; ks < 8; ks++) {
            uint32_t pa[4];
            pa[0] = pack2h(s[2*ks][0],   s[2*ks][1]);
            pa[1] = pack2h(s[2*ks][2],   s[2*ks][3]);
            pa[2] = pack2h(s[2*ks+1][0], s[2*ks+1][1]);
            pa[3] = pack2h(s[2*ks+1][2], s[2*ks+1][3]);
            #pragma unroll
            for (int nv = 0; nv < 4; nv++) {
                uint32_t va = base + 2*FA_TILE + (ks * 16 + vrow) * FA_ROWF
                              + (nv * 16 + vcol) * 2;
                uint32_t v4[4];
                ldsm_x4_t(v4, va);
                mma16816b(o[2*nv],   pa, v4[0], v4[1]);
                mma16816b(o[2*nv+1], pa, v4[2], v4[3]);
            }
        }
    }

    // ---- finalize ----
    l0v += __shfl_xor_sync(0xffffffffu, l0v, 1);
    l0v += __shfl_xor_sync(0xffffffffu, l0v, 2);
    l1v += __shfl_xor_sync(0xffffffffu, l1v, 1);
    l1v += __shfl_xor_sync(0xffffffffu, l1v, 2);
    float inv0 = 1.f / l0v, inv1 = 1.f / l1v;
    size_t orow0 = (size_t)(b * SS + qrow0) * DD + h * HDIM;
    size_t orow1 = orow0 + (size_t)8 * DD;
    #pragma unroll
    for (int nf = 0; nf < 8; nf++) {
        int col = nf * 8 + 2 * t;
        store_h2(g_vo, orow0 + col, o[nf][0] * inv0, o[nf][1] * inv0);
        store_h2(g_vo, orow1 + col, o[nf][2] * inv1, o[nf][3] * inv1);
    }
}

// ================= weight transpose+split (fp16) =================
__global__ __launch_bounds__(256) void wsplit_t(const float* __restrict__ W,
                                                __half* __restrict__ hi,
                                                __half* __restrict__ lo,
                                                int Kdim, int Ndim) {
    __shared__ float t[32][33];
    size_t loff = (size_t)blockIdx.z * Kdim * Ndim;
    const float* Wl = W + loff;
    __half* hil = hi + loff;
    __half* lol = lo + loff;
    int k0 = blockIdx.y * 32, n0 = blockIdx.x * 32;
    int tx = threadIdx.x, ty = threadIdx.y;
    #pragma unroll
    for (int i = 0; i < 32; i += 8)
        t[ty + i][tx] = Wl[(size_t)(k0 + ty + i) * Ndim + n0 + tx];
    __syncthreads();
    #pragma unroll
    for (int i = 0; i < 32; i += 8) {
        int n = n0 + ty + i, k = k0 + tx;
        float v = t[tx][ty + i];
        __half hv = __float2half_rn(v);
        hil[(size_t)n * Kdim + k] = hv;
        lol[(size_t)n * Kdim + k] = __float2half_rn(v - __half2float(hv));
    }
}

// ================= embed + PE =================
__global__ __launch_bounds__(256) void embed_kernel(const int* __restrict__ tokens,
                                                    const float* __restrict__ emb,
                                                    float* __restrict__ x,
                                                    __half* __restrict__ xh) {
    int row = blockIdx.x;
    int s = row & (SS - 1);
    int tok = tokens[row];
    const float* e = emb + (size_t)tok * DD;
    int d0 = threadIdx.x * 4;
    float v[4];
    #pragma unroll
    for (int j = 0; j < 4; j++) {
        int d = d0 + j;
        int i2 = d & ~1;
        float denom = powf(10000.0f, (float)i2 / (float)DD);
        float ang = (float)s / denom;
        float pe = (d & 1) ? cosf(ang) : sinf(ang);
        v[j] = e[d] + pe;
    }
    size_t base = (size_t)row * DD + d0;
    *(float4*)(x + base) = make_float4(v[0], v[1], v[2], v[3]);
    store_h2(xh, base, v[0], v[1]);
    store_h2(xh, base + 2, v[2], v[3]);
}

// ================= residual + LayerNorm =================
__device__ __forceinline__ float warpReduceSum(float v) {
    #pragma unroll
    for (int o = 16; o; o >>= 1) v += __shfl_xor_sync(0xffffffffu, v, o);
    return v;
}
__device__ __forceinline__ float blockReduceSum(float v, float* sh) {
    v = warpReduceSum(v);
    int w = threadIdx.x >> 5;
    __syncthreads();
    if ((threadIdx.x & 31) == 0) sh[w] = v;
    __syncthreads();
    if (threadIdx.x < 32) {
        float t = (threadIdx.x < 8) ? sh[threadIdx.x] : 0.f;
        t = warpReduceSum(t);
        if (threadIdx.x == 0) sh[0] = t;
    }
    __syncthreads();
    return sh[0];
}

__global__ __launch_bounds__(256) void ln_kernel(const float* __restrict__ x,
                                                 const float* __restrict__ y,
                                                 const float* __restrict__ gamma,
                                                 const float* __restrict__ beta,
                                                 float* __restrict__ out,
                                                 __half* __restrict__ oh) {
    __shared__ float sh[8];
    size_t row = blockIdx.x;
    int d0 = threadIdx.x * 4;
    float4 a = *(const float4*)(x + row * DD + d0);
    float4 b4 = *(const float4*)(y + row * DD + d0);
    float z[4] = { a.x + b4.x, a.y + b4.y, a.z + b4.z, a.w + b4.w };
    float ssum = z[0] + z[1] + z[2] + z[3];
    ssum = blockReduceSum(ssum, sh);
    float mean = ssum * (1.0f / DD);
    float d2 = 0.f;
    #pragma unroll
    for (int e = 0; e < 4; e++) { float u = z[e] - mean; d2 += u * u; }
    d2 = blockReduceSum(d2, sh);
    float inv = rsqrtf(d2 * (1.0f / DD) + EPSV);
    float4 g4 = *(const float4*)(gamma + d0);
    float4 be4 = *(const float4*)(beta + d0);
    float o0 = g4.x * ((z[0] - mean) * inv) + be4.x;
    float o1 = g4.y * ((z[1] - mean) * inv) + be4.y;
    float o2 = g4.z * ((z[2] - mean) * inv) + be4.z;
    float o3 = g4.w * ((z[3] - mean) * inv) + be4.w;
    size_t base = row * DD + d0;
    *(float4*)(out + base) = make_float4(o0, o1, o2, o3);
    store_h2(oh, base, o0, o1);
    store_h2(oh, base + 2, o2, o3);
}

// ================= orchestration =================
extern "C" void kernel_launch(void* const* d_in, const int* in_sizes, int n_in,
                              void* d_out, int out_size) {
    const int*   tokens = (const int*)d_in[0];
    const float* mask   = (const float*)d_in[1];
    const float* emb    = (const float*)d_in[2];
    const float* qkv_w  = (const float*)d_in[3];
    const float* qkv_b  = (const float*)d_in[4];
    const float* out_w  = (const float*)d_in[5];
    const float* out_b  = (const float*)d_in[6];
    const float* w1     = (const float*)d_in[7];
    const float* b1     = (const float*)d_in[8];
    const float* w2     = (const float*)d_in[9];
    const float* b2     = (const float*)d_in[10];
    const float* gamma  = (const float*)d_in[11];
    const float* beta   = (const float*)d_in[12];
    float* out = (float*)d_out;

    float *px, *py;
    cudaGetSymbolAddress((void**)&px, g_x);
    cudaGetSymbolAddress((void**)&py, g_y);
    __half *pa, *pffa, *pvo;
    __half *pqh, *pql, *poh, *pol, *p1h, *p1l, *p2h, *p2l;
    cudaGetSymbolAddress((void**)&pa,   g_a);
    cudaGetSymbolAddress((void**)&pffa, g_ffa);
    cudaGetSymbolAddress((void**)&pvo,  g_vo);
    cudaGetSymbolAddress((void**)&pqh,  g_wqkv_hi);
    cudaGetSymbolAddress((void**)&pql,  g_wqkv_lo);
    cudaGetSymbolAddress((void**)&poh,  g_wout_hi);
    cudaGetSymbolAddress((void**)&pol,  g_wout_lo);
    cudaGetSymbolAddress((void**)&p1h,  g_w1_hi);
    cudaGetSymbolAddress((void**)&p1l,  g_w1_lo);
    cudaGetSymbolAddress((void**)&p2h,  g_w2_hi);
    cudaGetSymbolAddress((void**)&p2l,  g_w2_lo);

    cudaFuncSetAttribute(gemm_mma<0>, cudaFuncAttributeMaxDynamicSharedMemorySize, GT_SMEM);
    cudaFuncSetAttribute(gemm_mma<1>, cudaFuncAttributeMaxDynamicSharedMemorySize, GT_SMEM);
    cudaFuncSetAttribute(gemm_mma<2>, cudaFuncAttributeMaxDynamicSharedMemorySize, GT_SMEM);
    cudaFuncSetAttribute(flash_attn, cudaFuncAttributeMaxDynamicSharedMemorySize, FA_SMEM);

    wsplit_t<<<dim3(3 * DD / 32, DD / 32, LL), dim3(32, 8)>>>(qkv_w, pqh, pql, DD, 3 * DD);
    wsplit_t<<<dim3(DD / 32, DD / 32, LL),     dim3(32, 8)>>>(out_w, poh, pol, DD, DD);
    wsplit_t<<<dim3(FF / 32, DD / 32, LL),     dim3(32, 8)>>>(w1, p1h, p1l, DD, FF);
    wsplit_t<<<dim3(DD / 32, FF / 32, LL),     dim3(32, 8)>>>(w2, p2h, p2l, FF, DD);

    embed_kernel<<<MM, 256>>>(tokens, emb, px, pa);

    for (int i = 0; i < LL; i++) {
        size_t l = (size_t)i;
        gemm_mma<2><<<dim3(3 * DD / GBN, MM / GBM), 256, GT_SMEM>>>(
            pa, pqh + l * 3 * DD * DD, pql + l * 3 * DD * DD,
            qkv_b + l * 3 * DD, nullptr, nullptr, 3 * DD, DD);
        flash_attn<<<dim3(SS / 128, BB * HH), 256, FA_SMEM>>>(mask);
        gemm_mma<0><<<dim3(DD / GBN, MM / GBM), 256, GT_SMEM>>>(
            pvo, poh + l * DD * DD, pol + l * DD * DD,
            out_b + l * DD, py, nullptr, DD, DD);
        ln_kernel<<<MM, 256>>>(px, py, gamma + l * DD, beta + l * DD, px, pa);
        gemm_mma<1><<<dim3(FF / GBN, MM / GBM), 256, GT_SMEM>>>(
            pa, p1h + l * DD * FF, p1l + l * DD * FF,
            b1 + l * FF, nullptr, pffa, FF, DD);
        gemm_mma<0><<<dim3(DD / GBN, MM / GBM), 256, GT_SMEM>>>(
            pffa, p2h + l * FF * DD, p2l + l * FF * DD,
            b2 + l * DD, py, nullptr, DD, FF);
        ln_kernel<<<MM, 256>>>(px, py, gamma + l * DD, beta + l * DD,
                               (i == LL - 1) ? out : px, pa);
    }
}

// round 7
// speedup vs baseline: 4.4263x; 1.4161x over previous
#include <cuda_runtime.h>
#include <cuda_fp16.h>
#include <math.h>
#include <stdint.h>

#define BB 4
#define SS 1024
#define DD 1024
#define HH 16
#define HDIM 64
#define FF 4096
#define LL 6
#define MM (BB*SS)
#define EPSV 1e-5f

// ---------------- scratch (device globals; no allocation allowed) ----------------
__device__ float g_x[MM*DD];
__device__ float g_y[MM*DD];
__device__ __half g_a[MM*DD];
__device__ __half g_ffa[MM*FF];
__device__ __half g_q[BB*HH*SS*HDIM];
__device__ __half g_kh[BB*HH*SS*HDIM];
__device__ __half g_kl[BB*HH*SS*HDIM];
__device__ __half g_v[BB*HH*SS*HDIM];
__device__ __half g_vo[MM*DD];
// weights single fp16, [N,K] K-major
__device__ __half g_wqkv[(size_t)LL*3*DD*DD];
__device__ __half g_wout[(size_t)LL*DD*DD];
__device__ __half g_w1[(size_t)LL*DD*FF];
__device__ __half g_w2[(size_t)LL*FF*DD];

// ================= PTX building blocks =================
__device__ __forceinline__ uint32_t smem_u32(const void* p) {
    return (uint32_t)__cvta_generic_to_shared((void*)p);
}
__device__ __forceinline__ void ldsm_x4(uint32_t (&r)[4], uint32_t addr) {
    asm volatile("ldmatrix.sync.aligned.m8n8.x4.shared.b16 {%0,%1,%2,%3}, [%4];"
        : "=r"(r[0]), "=r"(r[1]), "=r"(r[2]), "=r"(r[3]) : "r"(addr));
}
__device__ __forceinline__ void ldsm_x4_t(uint32_t (&r)[4], uint32_t addr) {
    asm volatile("ldmatrix.sync.aligned.m8n8.x4.trans.shared.b16 {%0,%1,%2,%3}, [%4];"
        : "=r"(r[0]), "=r"(r[1]), "=r"(r[2]), "=r"(r[3]) : "r"(addr));
}
__device__ __forceinline__ void ldsm_x2(uint32_t (&r)[2], uint32_t addr) {
    asm volatile("ldmatrix.sync.aligned.m8n8.x2.shared.b16 {%0,%1}, [%2];"
        : "=r"(r[0]), "=r"(r[1]) : "r"(addr));
}
__device__ __forceinline__ void mma16816(float (&d)[4], const uint32_t (&a)[4],
                                         const uint32_t (&b)[2]) {
    asm volatile(
        "mma.sync.aligned.m16n8k16.row.col.f32.f16.f16.f32 "
        "{%0,%1,%2,%3}, {%4,%5,%6,%7}, {%8,%9}, {%0,%1,%2,%3};"
        : "+f"(d[0]), "+f"(d[1]), "+f"(d[2]), "+f"(d[3])
        : "r"(a[0]), "r"(a[1]), "r"(a[2]), "r"(a[3]), "r"(b[0]), "r"(b[1]));
}
__device__ __forceinline__ void mma16816b(float (&d)[4], const uint32_t (&a)[4],
                                          uint32_t b0, uint32_t b1) {
    asm volatile(
        "mma.sync.aligned.m16n8k16.row.col.f32.f16.f16.f32 "
        "{%0,%1,%2,%3}, {%4,%5,%6,%7}, {%8,%9}, {%0,%1,%2,%3};"
        : "+f"(d[0]), "+f"(d[1]), "+f"(d[2]), "+f"(d[3])
        : "r"(a[0]), "r"(a[1]), "r"(a[2]), "r"(a[3]), "r"(b0), "r"(b1));
}
__device__ __forceinline__ void cp16(uint32_t dst, const void* src) {
    asm volatile("cp.async.cg.shared.global [%0], [%1], 16;" :: "r"(dst), "l"(src));
}
#define CP_COMMIT() asm volatile("cp.async.commit_group;" ::: "memory")
#define CP_WAIT2()  asm volatile("cp.async.wait_group 2;" ::: "memory")
#define CP_WAIT1()  asm volatile("cp.async.wait_group 1;" ::: "memory")
#define CP_WAIT0()  asm volatile("cp.async.wait_group 0;" ::: "memory")

__device__ __forceinline__ void store_h2(__half* p, size_t idx, float a, float b) {
    *(__half2*)(p + idx) = __floats2half2_rn(a, b);
}
__device__ __forceinline__ void store_hilo(__half* ph, __half* pl, size_t idx,
                                           float a, float b) {
    __half ha = __float2half_rn(a), hb = __float2half_rn(b);
    *(__half2*)(ph + idx) = __half2(ha, hb);
    *(__half2*)(pl + idx) = __floats2half2_rn(a - __half2float(ha),
                                              b - __half2float(hb));
}
__device__ __forceinline__ uint32_t pack2h(float a, float b) {
    __half2 h = __floats2half2_rn(a, b);
    return *(uint32_t*)&h;
}

// ================= tensor-core GEMM (fp16 single-term, 4-stage pipeline) =========
#define GBM 128
#define GBN 128
#define GBK 32
#define ROWB 80
#define TILEB (128*ROWB)
#define STAGEB (2*TILEB)
#define NSTG 4
#define GT_SMEM (NSTG*STAGEB)

template<int EPI>
__global__ __launch_bounds__(256, 1) void gemm_mma(
    const __half* __restrict__ A, const __half* __restrict__ B,
    const float* __restrict__ bias, float* __restrict__ Cf,
    __half* __restrict__ Ch, int N, int K)
{
    extern __shared__ char sm[];
    uint32_t sb = smem_u32(sm);
    int tid = threadIdx.x;
    int warp = tid >> 5, lane = tid & 31;
    int wm = warp >> 2, wn = warp & 3;
    int m0 = blockIdx.y * GBM, n0 = blockIdx.x * GBN;

    float acc[4][4][4];
    #pragma unroll
    for (int i = 0; i < 4; i++)
        #pragma unroll
        for (int j = 0; j < 4; j++)
            #pragma unroll
            for (int e = 0; e < 4; e++) acc[i][j][e] = 0.f;

    auto load_stage = [&](int s, int k0) {
        uint32_t base = sb + s * STAGEB;
        #pragma unroll
        for (int j = 0; j < 4; j++) {
            int ch = tid + 256 * j;
            int tile = ch >> 9, r = (ch >> 2) & 127, c = ch & 3;
            const __half* src = (tile == 0) ? A + (size_t)(m0 + r) * K + k0 + c * 8
                                            : B + (size_t)(n0 + r) * K + k0 + c * 8;
            cp16(base + tile * TILEB + r * ROWB + c * 16, src);
        }
    };

    int T = K / GBK;
    load_stage(0, 0);          CP_COMMIT();
    load_stage(1, GBK);        CP_COMMIT();
    load_stage(2, 2 * GBK);    CP_COMMIT();

    int a_r = lane & 15, a_c8 = (lane >> 4) * 8;
    int b_r = lane & 7,  b_c8 = ((lane >> 3) & 1) * 8;

    for (int t = 0; t < T; t++) {
        if (t + 2 < T)      { CP_WAIT2(); }
        else if (t + 1 < T) { CP_WAIT1(); }
        else                { CP_WAIT0(); }
        __syncthreads();
        if (t + 3 < T) { load_stage((t + 3) & (NSTG - 1), (t + 3) * GBK); CP_COMMIT(); }

        uint32_t base = sb + (t & (NSTG - 1)) * STAGEB;
        #pragma unroll
        for (int kk = 0; kk < 2; kk++) {
            uint32_t af[4][4], bf[4][2];
            #pragma unroll
            for (int mi = 0; mi < 4; mi++) {
                int row = wm * 64 + mi * 16 + a_r;
                ldsm_x4(af[mi], base + row * ROWB + (kk * 16 + a_c8) * 2);
            }
            #pragma unroll
            for (int ni = 0; ni < 4; ni++) {
                int row = wn * 32 + ni * 8 + b_r;
                ldsm_x2(bf[ni], base + TILEB + row * ROWB + (kk * 16 + b_c8) * 2);
            }
            #pragma unroll
            for (int mi = 0; mi < 4; mi++)
                #pragma unroll
                for (int ni = 0; ni < 4; ni++)
                    mma16816(acc[mi][ni], af[mi], bf[ni]);
        }
    }

    int qr = lane >> 2, qc = (lane & 3) * 2;
    #pragma unroll
    for (int mi = 0; mi < 4; mi++) {
        #pragma unroll
        for (int ni = 0; ni < 4; ni++) {
            int gr = m0 + wm * 64 + mi * 16 + qr;
            int gc = n0 + wn * 32 + ni * 8 + qc;
            float b0 = bias[gc], b1 = bias[gc + 1];
            float v00 = acc[mi][ni][0] + b0, v01 = acc[mi][ni][1] + b1;
            float v10 = acc[mi][ni][2] + b0, v11 = acc[mi][ni][3] + b1;
            if (EPI == 0) {
                *(float2*)(Cf + (size_t)gr * N + gc)       = make_float2(v00, v01);
                *(float2*)(Cf + (size_t)(gr + 8) * N + gc) = make_float2(v10, v11);
            } else if (EPI == 1) {
                v00 = fmaxf(v00, 0.f); v01 = fmaxf(v01, 0.f);
                v10 = fmaxf(v10, 0.f); v11 = fmaxf(v11, 0.f);
                store_h2(Ch, (size_t)gr * N + gc,       v00, v01);
                store_h2(Ch, (size_t)(gr + 8) * N + gc, v10, v11);
            } else {
                int hh = gc / 192, inner = gc - hh * 192;
                int ty = inner >> 6, d = inner & 63;
                int bb = gr >> 10, si = gr & 1023;
                size_t dst = ((size_t)(bb * HH + hh) * SS + si) * HDIM + d;
                if (ty == 0) {
                    store_h2(g_q, dst,            v00 * 0.125f, v01 * 0.125f);
                    store_h2(g_q, dst + 8 * HDIM, v10 * 0.125f, v11 * 0.125f);
                } else if (ty == 1) {
                    store_hilo(g_kh, g_kl, dst,            v00, v01);
                    store_hilo(g_kh, g_kl, dst + 8 * HDIM, v10, v11);
                } else {
                    store_h2(g_v, dst,            v00, v01);
                    store_h2(g_v, dst + 8 * HDIM, v10, v11);
                }
            }
        }
    }
}

// ================= flash attention (fp16, Q single, K hi/lo, V single) ===========
#define FA_ROWF 144
#define FA_TILE (128*FA_ROWF)
#define FA_STAGE (3*FA_TILE)
#define FA_NSTG 3
#define FA_SMEM (FA_NSTG*FA_STAGE)

__global__ __launch_bounds__(256, 1) void flash_attn(const float* __restrict__ mask)
{
    extern __shared__ char sm[];
    uint32_t sb = smem_u32(sm);
    int tid = threadIdx.x, lane = tid & 31, w = tid >> 5;
    int qt = blockIdx.x, bh = blockIdx.y;
    int b = bh >> 4, h = bh & 15;
    size_t head = (size_t)bh * SS * HDIM;

    #pragma unroll
    for (int j = 0; j < 4; j++) {
        int ch = tid + 256 * j;
        int row = (ch >> 3) & 127, c = ch & 7;
        cp16(sb + row * FA_ROWF + c * 16,
             g_q + head + (size_t)(qt * 128 + row) * HDIM + c * 8);
    }
    CP_COMMIT(); CP_WAIT0();
    __syncthreads();

    uint32_t qf[4][4];
    {
        int ar = lane & 15, ac = (lane >> 4) * 8;
        #pragma unroll
        for (int kb = 0; kb < 4; kb++)
            ldsm_x4(qf[kb], sb + (w * 16 + ar) * FA_ROWF + (kb * 16 + ac) * 2);
    }
    __syncthreads();

    auto load_kv = [&](int s, int kt) {
        uint32_t base = sb + s * FA_STAGE;
        size_t goff = head + (size_t)(kt * 128) * HDIM;
        #pragma unroll
        for (int j = 0; j < 12; j++) {
            int ch = tid + 256 * j;
            int tile = ch >> 10, row = (ch >> 3) & 127, c = ch & 7;
            const __half* sp = (tile == 0) ? g_kh : (tile == 1) ? g_kl : g_v;
            cp16(base + tile * FA_TILE + row * FA_ROWF + c * 16,
                 sp + goff + (size_t)row * HDIM + c * 8);
        }
    };
    load_kv(0, 0); CP_COMMIT();
    load_kv(1, 1); CP_COMMIT();

    int g = lane >> 2, t = lane & 3;
    int krow = (lane & 7) + ((lane >> 4) & 1) * 8, kcol = ((lane >> 3) & 1) * 8;
    int vrow = (lane & 7) + ((lane >> 3) & 1) * 8, vcol = ((lane >> 4) & 1) * 8;
    int qrow0 = qt * 128 + w * 16 + g;
    const float* mrow0 = mask + ((size_t)(b * SS + qrow0)) * SS;

    float m0v = -1e30f, m1v = -1e30f, l0v = 0.f, l1v = 0.f;
    float o[8][4];
    #pragma unroll
    for (int nf = 0; nf < 8; nf++)
        #pragma unroll
        for (int e = 0; e < 4; e++) o[nf][e] = 0.f;

    const int T = 8;
    for (int kt = 0; kt < T; kt++) {
        if (kt < T - 1) { CP_WAIT1(); } else { CP_WAIT0(); }
        __syncthreads();
        if (kt + 2 < T) { load_kv((kt + 2) % FA_NSTG, kt + 2); CP_COMMIT(); }
        uint32_t base = sb + (kt % FA_NSTG) * FA_STAGE;

        float s[16][4];
        #pragma unroll
        for (int np = 0; np < 8; np++) {
            #pragma unroll
            for (int e = 0; e < 4; e++) { s[2*np][e] = 0.f; s[2*np+1][e] = 0.f; }
            #pragma unroll
            for (int kb = 0; kb < 4; kb++) {
                uint32_t ka = base + (np * 16 + krow) * FA_ROWF + (kb * 16 + kcol) * 2;
                uint32_t kh4[4], kl4[4];
                ldsm_x4(kh4, ka);
                ldsm_x4(kl4, ka + FA_TILE);
                mma16816b(s[2*np],   qf[kb], kh4[0], kh4[1]);
                mma16816b(s[2*np+1], qf[kb], kh4[2], kh4[3]);
                mma16816b(s[2*np],   qf[kb], kl4[0], kl4[1]);
                mma16816b(s[2*np+1], qf[kb], kl4[2], kl4[3]);
            }
        }

        float mx0 = -1e30f, mx1 = -1e30f;
        #pragma unroll
        for (int ni = 0; ni < 16; ni++) {
            const float* mp = mrow0 + kt * 128 + ni * 8 + 2 * t;
            float2 mk0 = *(const float2*)mp;
            float2 mk1 = *(const float2*)(mp + 8 * SS);
            s[ni][0] += mk0.x; s[ni][1] += mk0.y;
            s[ni][2] += mk1.x; s[ni][3] += mk1.y;
            mx0 = fmaxf(mx0, fmaxf(s[ni][0], s[ni][1]));
            mx1 = fmaxf(mx1, fmaxf(s[ni][2], s[ni][3]));
        }
        mx0 = fmaxf(mx0, __shfl_xor_sync(0xffffffffu, mx0, 1));
        mx0 = fmaxf(mx0, __shfl_xor_sync(0xffffffffu, mx0, 2));
        mx1 = fmaxf(mx1, __shfl_xor_sync(0xffffffffu, mx1, 1));
        mx1 = fmaxf(mx1, __shfl_xor_sync(0xffffffffu, mx1, 2));
        float mn0 = fmaxf(m0v, mx0), mn1 = fmaxf(m1v, mx1);
        float a0 = __expf(m0v - mn0), a1 = __expf(m1v - mn1);
        m0v = mn0; m1v = mn1;
        l0v *= a0; l1v *= a1;
        #pragma unroll
        for (int nf = 0; nf < 8; nf++) {
            o[nf][0] *= a0; o[nf][1] *= a0; o[nf][2] *= a1; o[nf][3] *= a1;
        }
        #pragma unroll
        for (int ni = 0; ni < 16; ni++) {
            s[ni][0] = __expf(s[ni][0] - mn0); s[ni][1] = __expf(s[ni][1] - mn0);
            s[ni][2] = __expf(s[ni][2] - mn1); s[ni][3] = __expf(s[ni][3] - mn1);
            l0v += s[ni][0] + s[ni][1];
            l1v += s[ni][2] + s[ni][3];
        }

        #pragma unroll
        for (int ks = 0; ks < 8; ks++) {
            uint32_t pa[4];
            pa[0] = pack2h(s[2*ks][0],   s[2*ks][1]);
            pa[1] = pack2h(s[2*ks][2],   s[2*ks][3]);
            pa[2] = pack2h(s[2*ks+1][0], s[2*ks+1][1]);
            pa[3] = pack2h(s[2*ks+1][2], s[2*ks+1][3]);
            #pragma unroll
            for (int nv = 0; nv < 4; nv++) {
                uint32_t va = base + 2*FA_TILE + (ks * 16 + vrow) * FA_ROWF
                              + (nv * 16 + vcol) * 2;
                uint32_t v4[4];
                ldsm_x4_t(v4, va);
                mma16816b(o[2*nv],   pa, v4[0], v4[1]);
                mma16816b(o[2*nv+1], pa, v4[2], v4[3]);
            }
        }
    }

    l0v += __shfl_xor_sync(0xffffffffu, l0v, 1);
    l0v += __shfl_xor_sync(0xffffffffu, l0v, 2);
    l1v += __shfl_xor_sync(0xffffffffu, l1v, 1);
    l1v += __shfl_xor_sync(0xffffffffu, l1v, 2);
    float inv0 = 1.f / l0v, inv1 = 1.f / l1v;
    size_t orow0 = (size_t)(b * SS + qrow0) * DD + h * HDIM;
    size_t orow1 = orow0 + (size_t)8 * DD;
    #pragma unroll
    for (int nf = 0; nf < 8; nf++) {
        int col = nf * 8 + 2 * t;
        store_h2(g_vo, orow0 + col, o[nf][0] * inv0, o[nf][1] * inv0);
        store_h2(g_vo, orow1 + col, o[nf][2] * inv1, o[nf][3] * inv1);
    }
}

// ================= weight transpose (fp16 single) =================
__global__ __launch_bounds__(256) void wsplit_t(const float* __restrict__ W,
                                                __half* __restrict__ hi,
                                                int Kdim, int Ndim) {
    __shared__ float t[32][33];
    size_t loff = (size_t)blockIdx.z * Kdim * Ndim;
    const float* Wl = W + loff;
    __half* hil = hi + loff;
    int k0 = blockIdx.y * 32, n0 = blockIdx.x * 32;
    int tx = threadIdx.x, ty = threadIdx.y;
    #pragma unroll
    for (int i = 0; i < 32; i += 8)
        t[ty + i][tx] = Wl[(size_t)(k0 + ty + i) * Ndim + n0 + tx];
    __syncthreads();
    #pragma unroll
    for (int i = 0; i < 32; i += 8) {
        int n = n0 + ty + i, k = k0 + tx;
        hil[(size_t)n * Kdim + k] = __float2half_rn(t[tx][ty + i]);
    }
}

// ================= embed + PE =================
__global__ __launch_bounds__(256) void embed_kernel(const int* __restrict__ tokens,
                                                    const float* __restrict__ emb,
                                                    float* __restrict__ x,
                                                    __half* __restrict__ xh) {
    int row = blockIdx.x;
    int s = row & (SS - 1);
    int tok = tokens[row];
    const float* e = emb + (size_t)tok * DD;
    int d0 = threadIdx.x * 4;
    float v[4];
    #pragma unroll
    for (int j = 0; j < 4; j++) {
        int d = d0 + j;
        int i2 = d & ~1;
        float denom = powf(10000.0f, (float)i2 / (float)DD);
        float ang = (float)s / denom;
        float pe = (d & 1) ? cosf(ang) : sinf(ang);
        v[j] = e[d] + pe;
    }
    size_t base = (size_t)row * DD + d0;
    *(float4*)(x + base) = make_float4(v[0], v[1], v[2], v[3]);
    store_h2(xh, base, v[0], v[1]);
    store_h2(xh, base + 2, v[2], v[3]);
}

// ================= residual + LayerNorm =================
__device__ __forceinline__ float warpReduceSum(float v) {
    #pragma unroll
    for (int o = 16; o; o >>= 1) v += __shfl_xor_sync(0xffffffffu, v, o);
    return v;
}
__device__ __forceinline__ float blockReduceSum(float v, float* sh) {
    v = warpReduceSum(v);
    int w = threadIdx.x >> 5;
    __syncthreads();
    if ((threadIdx.x & 31) == 0) sh[w] = v;
    __syncthreads();
    if (threadIdx.x < 32) {
        float t = (threadIdx.x < 8) ? sh[threadIdx.x] : 0.f;
        t = warpReduceSum(t);
        if (threadIdx.x == 0) sh[0] = t;
    }
    __syncthreads();
    return sh[0];
}

__global__ __launch_bounds__(256) void ln_kernel(const float* __restrict__ x,
                                                 const float* __restrict__ y,
                                                 const float* __restrict__ gamma,
                                                 const float* __restrict__ beta,
                                                 float* __restrict__ out,
                                                 __half* __restrict__ oh) {
    __shared__ float sh[8];
    size_t row = blockIdx.x;
    int d0 = threadIdx.x * 4;
    float4 a = *(const float4*)(x + row * DD + d0);
    float4 b4 = *(const float4*)(y + row * DD + d0);
    float z[4] = { a.x + b4.x, a.y + b4.y, a.z + b4.z, a.w + b4.w };
    float ssum = z[0] + z[1] + z[2] + z[3];
    ssum = blockReduceSum(ssum, sh);
    float mean = ssum * (1.0f / DD);
    float d2 = 0.f;
    #pragma unroll
    for (int e = 0; e < 4; e++) { float u = z[e] - mean; d2 += u * u; }
    d2 = blockReduceSum(d2, sh);
    float inv = rsqrtf(d2 * (1.0f / DD) + EPSV);
    float4 g4 = *(const float4*)(gamma + d0);
    float4 be4 = *(const float4*)(beta + d0);
    float o0 = g4.x * ((z[0] - mean) * inv) + be4.x;
    float o1 = g4.y * ((z[1] - mean) * inv) + be4.y;
    float o2 = g4.z * ((z[2] - mean) * inv) + be4.z;
    float o3 = g4.w * ((z[3] - mean) * inv) + be4.w;
    size_t base = row * DD + d0;
    *(float4*)(out + base) = make_float4(o0, o1, o2, o3);
    store_h2(oh, base, o0, o1);
    store_h2(oh, base + 2, o2, o3);
}

// ================= orchestration =================
extern "C" void kernel_launch(void* const* d_in, const int* in_sizes, int n_in,
                              void* d_out, int out_size) {
    const int*   tokens = (const int*)d_in[0];
    const float* mask   = (const float*)d_in[1];
    const float* emb    = (const float*)d_in[2];
    const float* qkv_w  = (const float*)d_in[3];
    const float* qkv_b  = (const float*)d_in[4];
    const float* out_w  = (const float*)d_in[5];
    const float* out_b  = (const float*)d_in[6];
    const float* w1     = (const float*)d_in[7];
    const float* b1     = (const float*)d_in[8];
    const float* w2     = (const float*)d_in[9];
    const float* b2     = (const float*)d_in[10];
    const float* gamma  = (const float*)d_in[11];
    const float* beta   = (const float*)d_in[12];
    float* out = (float*)d_out;

    float *px, *py;
    cudaGetSymbolAddress((void**)&px, g_x);
    cudaGetSymbolAddress((void**)&py, g_y);
    __half *pa, *pffa, *pvo, *pwq, *pwo, *pw1, *pw2;
    cudaGetSymbolAddress((void**)&pa,   g_a);
    cudaGetSymbolAddress((void**)&pffa, g_ffa);
    cudaGetSymbolAddress((void**)&pvo,  g_vo);
    cudaGetSymbolAddress((void**)&pwq,  g_wqkv);
    cudaGetSymbolAddress((void**)&pwo,  g_wout);
    cudaGetSymbolAddress((void**)&pw1,  g_w1);
    cudaGetSymbolAddress((void**)&pw2,  g_w2);

    cudaFuncSetAttribute(gemm_mma<0>, cudaFuncAttributeMaxDynamicSharedMemorySize, GT_SMEM);
    cudaFuncSetAttribute(gemm_mma<1>, cudaFuncAttributeMaxDynamicSharedMemorySize, GT_SMEM);
    cudaFuncSetAttribute(gemm_mma<2>, cudaFuncAttributeMaxDynamicSharedMemorySize, GT_SMEM);
    cudaFuncSetAttribute(flash_attn, cudaFuncAttributeMaxDynamicSharedMemorySize, FA_SMEM);

    wsplit_t<<<dim3(3 * DD / 32, DD / 32, LL), dim3(32, 8)>>>(qkv_w, pwq, DD, 3 * DD);
    wsplit_t<<<dim3(DD / 32, DD / 32, LL),     dim3(32, 8)>>>(out_w, pwo, DD, DD);
    wsplit_t<<<dim3(FF / 32, DD / 32, LL),     dim3(32, 8)>>>(w1, pw1, DD, FF);
    wsplit_t<<<dim3(DD / 32, FF / 32, LL),     dim3(32, 8)>>>(w2, pw2, FF, DD);

    embed_kernel<<<MM, 256>>>(tokens, emb, px, pa);

    for (int i = 0; i < LL; i++) {
        size_t l = (size_t)i;
        gemm_mma<2><<<dim3(3 * DD / GBN, MM / GBM), 256, GT_SMEM>>>(
            pa, pwq + l * 3 * DD * DD, qkv_b + l * 3 * DD, nullptr, nullptr, 3 * DD, DD);
        flash_attn<<<dim3(SS / 128, BB * HH), 256, FA_SMEM>>>(mask);
        gemm_mma<0><<<dim3(DD / GBN, MM / GBM), 256, GT_SMEM>>>(
            pvo, pwo + l * DD * DD, out_b + l * DD, py, nullptr, DD, DD);
        ln_kernel<<<MM, 256>>>(px, py, gamma + l * DD, beta + l * DD, px, pa);
        gemm_mma<1><<<dim3(FF / GBN, MM / GBM), 256, GT_SMEM>>>(
            pa, pw1 + l * DD * FF, b1 + l * FF, nullptr, pffa, FF, DD);
        gemm_mma<0><<<dim3(DD / GBN, MM / GBM), 256, GT_SMEM>>>(
            pffa, pw2 + l * FF * DD, b2 + l * DD, py, nullptr, DD, FF);
        ln_kernel<<<MM, 256>>>(px, py, gamma + l * DD, beta + l * DD,
                               (i == LL - 1) ? out : px, pa);
    }
}

// round 8
// speedup vs baseline: 4.8289x; 1.0910x over previous
#include <cuda_runtime.h>
#include <cuda_fp16.h>
#include <math.h>
#include <stdint.h>

#define BB 4
#define SS 1024
#define DD 1024
#define HH 16
#define HDIM 64
#define FF 4096
#define LL 6
#define MM (BB*SS)
#define EPSV 1e-5f

// ---------------- scratch (device globals; no allocation allowed) ----------------
__device__ float g_x[MM*DD];
__device__ float g_y[MM*DD];
__device__ __half g_a[MM*DD];
__device__ __half g_ffa[MM*FF];
__device__ __half g_q[BB*HH*SS*HDIM];
__device__ __half g_k[BB*HH*SS*HDIM];
__device__ __half g_v[BB*HH*SS*HDIM];
__device__ __half g_vo[MM*DD];
__device__ __half g_wqkv[(size_t)LL*3*DD*DD];
__device__ __half g_wout[(size_t)LL*DD*DD];
__device__ __half g_w1[(size_t)LL*DD*FF];
__device__ __half g_w2[(size_t)LL*FF*DD];

// ================= PTX building blocks =================
__device__ __forceinline__ uint32_t smem_u32(const void* p) {
    return (uint32_t)__cvta_generic_to_shared((void*)p);
}
__device__ __forceinline__ void ldsm_x4(uint32_t (&r)[4], uint32_t addr) {
    asm volatile("ldmatrix.sync.aligned.m8n8.x4.shared.b16 {%0,%1,%2,%3}, [%4];"
        : "=r"(r[0]), "=r"(r[1]), "=r"(r[2]), "=r"(r[3]) : "r"(addr));
}
__device__ __forceinline__ void ldsm_x4_t(uint32_t (&r)[4], uint32_t addr) {
    asm volatile("ldmatrix.sync.aligned.m8n8.x4.trans.shared.b16 {%0,%1,%2,%3}, [%4];"
        : "=r"(r[0]), "=r"(r[1]), "=r"(r[2]), "=r"(r[3]) : "r"(addr));
}
__device__ __forceinline__ void mma16816b(float (&d)[4], const uint32_t (&a)[4],
                                          uint32_t b0, uint32_t b1) {
    asm volatile(
        "mma.sync.aligned.m16n8k16.row.col.f32.f16.f16.f32 "
        "{%0,%1,%2,%3}, {%4,%5,%6,%7}, {%8,%9}, {%0,%1,%2,%3};"
        : "+f"(d[0]), "+f"(d[1]), "+f"(d[2]), "+f"(d[3])
        : "r"(a[0]), "r"(a[1]), "r"(a[2]), "r"(a[3]), "r"(b0), "r"(b1));
}
__device__ __forceinline__ void cp16(uint32_t dst, const void* src) {
    asm volatile("cp.async.cg.shared.global [%0], [%1], 16;" :: "r"(dst), "l"(src));
}
#define CP_COMMIT() asm volatile("cp.async.commit_group;" ::: "memory")
#define CP_WAIT2()  asm volatile("cp.async.wait_group 2;" ::: "memory")
#define CP_WAIT1()  asm volatile("cp.async.wait_group 1;" ::: "memory")
#define CP_WAIT0()  asm volatile("cp.async.wait_group 0;" ::: "memory")

__device__ __forceinline__ void store_h2(__half* p, size_t idx, float a, float b) {
    *(__half2*)(p + idx) = __floats2half2_rn(a, b);
}
__device__ __forceinline__ uint32_t pack2h(float a, float b) {
    __half2 h = __floats2half2_rn(a, b);
    return *(uint32_t*)&h;
}

// ================= tensor-core GEMM (fp16, 256x128 CTA tile, 4-stage) ============
#define GBM 256
#define GBN 128
#define GBK 32
#define ROWB 80
#define ATILE (256*ROWB)      // 20480
#define BTILE (128*ROWB)      // 10240
#define STAGEB (ATILE+BTILE)  // 30720
#define NSTG 4
#define GT_SMEM (NSTG*STAGEB) // 122880

template<int EPI>
__global__ __launch_bounds__(256, 1) void gemm_mma(
    const __half* __restrict__ A, const __half* __restrict__ B,
    const float* __restrict__ bias, float* __restrict__ Cf,
    __half* __restrict__ Ch, int N, int K)
{
    extern __shared__ char sm[];
    uint32_t sb = smem_u32(sm);
    int tid = threadIdx.x;
    int warp = tid >> 5, lane = tid & 31;
    int wm = warp >> 1, wn = warp & 1;           // 4 x 2 warp grid, warp tile 64x64
    int m0 = blockIdx.y * GBM, n0 = blockIdx.x * GBN;

    float acc[4][8][4];
    #pragma unroll
    for (int i = 0; i < 4; i++)
        #pragma unroll
        for (int j = 0; j < 8; j++)
            #pragma unroll
            for (int e = 0; e < 4; e++) acc[i][j][e] = 0.f;

    auto load_stage = [&](int s, int k0) {
        uint32_t base = sb + s * STAGEB;
        #pragma unroll
        for (int j = 0; j < 6; j++) {
            int ch = tid + 256 * j;              // 0..1535
            if (ch < 1024) {                     // A: 256 rows x 4 chunks
                int r = ch >> 2, c = ch & 3;
                cp16(base + r * ROWB + c * 16, A + (size_t)(m0 + r) * K + k0 + c * 8);
            } else {                             // B: 128 rows x 4 chunks
                int idx = ch - 1024;
                int r = idx >> 2, c = idx & 3;
                cp16(base + ATILE + r * ROWB + c * 16,
                     B + (size_t)(n0 + r) * K + k0 + c * 8);
            }
        }
    };

    int T = K / GBK;
    load_stage(0, 0);          CP_COMMIT();
    load_stage(1, GBK);        CP_COMMIT();
    load_stage(2, 2 * GBK);    CP_COMMIT();

    int a_r = lane & 15, a_c8 = (lane >> 4) * 8;

    for (int t = 0; t < T; t++) {
        if (t + 2 < T)      { CP_WAIT2(); }
        else if (t + 1 < T) { CP_WAIT1(); }
        else                { CP_WAIT0(); }
        __syncthreads();
        if (t + 3 < T) { load_stage((t + 3) & (NSTG - 1), (t + 3) * GBK); CP_COMMIT(); }

        uint32_t base = sb + (t & (NSTG - 1)) * STAGEB;
        #pragma unroll
        for (int kk = 0; kk < 2; kk++) {
            uint32_t af[4][4], bq[4][4];
            #pragma unroll
            for (int mi = 0; mi < 4; mi++) {
                int row = wm * 64 + mi * 16 + a_r;
                ldsm_x4(af[mi], base + row * ROWB + (kk * 16 + a_c8) * 2);
            }
            #pragma unroll
            for (int nb = 0; nb < 4; nb++) {
                int row = wn * 64 + nb * 16 + a_r;
                ldsm_x4(bq[nb], base + ATILE + row * ROWB + (kk * 16 + a_c8) * 2);
            }
            // bq[nb]: r0 = n0-7/k0-7, r1 = n8-15/k0-7, r2 = n0-7/k8-15, r3 = n8-15/k8-15
            #pragma unroll
            for (int mi = 0; mi < 4; mi++)
                #pragma unroll
                for (int nb = 0; nb < 4; nb++) {
                    mma16816b(acc[mi][2*nb],   af[mi], bq[nb][0], bq[nb][2]);
                    mma16816b(acc[mi][2*nb+1], af[mi], bq[nb][1], bq[nb][3]);
                }
        }
    }

    int qr = lane >> 2, qc = (lane & 3) * 2;
    #pragma unroll
    for (int mi = 0; mi < 4; mi++) {
        #pragma unroll
        for (int ni = 0; ni < 8; ni++) {
            int gr = m0 + wm * 64 + mi * 16 + qr;
            int gc = n0 + wn * 64 + ni * 8 + qc;
            float b0 = bias[gc], b1 = bias[gc + 1];
            float v00 = acc[mi][ni][0] + b0, v01 = acc[mi][ni][1] + b1;
            float v10 = acc[mi][ni][2] + b0, v11 = acc[mi][ni][3] + b1;
            if (EPI == 0) {
                *(float2*)(Cf + (size_t)gr * N + gc)       = make_float2(v00, v01);
                *(float2*)(Cf + (size_t)(gr + 8) * N + gc) = make_float2(v10, v11);
            } else if (EPI == 1) {
                v00 = fmaxf(v00, 0.f); v01 = fmaxf(v01, 0.f);
                v10 = fmaxf(v10, 0.f); v11 = fmaxf(v11, 0.f);
                store_h2(Ch, (size_t)gr * N + gc,       v00, v01);
                store_h2(Ch, (size_t)(gr + 8) * N + gc, v10, v11);
            } else {
                int hh = gc / 192, inner = gc - hh * 192;
                int ty = inner >> 6, d = inner & 63;
                int bb = gr >> 10, si = gr & 1023;
                size_t dst = ((size_t)(bb * HH + hh) * SS + si) * HDIM + d;
                int bb2 = (gr + 8) >> 10, si2 = (gr + 8) & 1023;
                size_t dst2 = ((size_t)(bb2 * HH + hh) * SS + si2) * HDIM + d;
                if (ty == 0) {
                    store_h2(g_q, dst,  v00 * 0.125f, v01 * 0.125f);
                    store_h2(g_q, dst2, v10 * 0.125f, v11 * 0.125f);
                } else if (ty == 1) {
                    store_h2(g_k, dst,  v00, v01);
                    store_h2(g_k, dst2, v10, v11);
                } else {
                    store_h2(g_v, dst,  v00, v01);
                    store_h2(g_v, dst2, v10, v11);
                }
            }
        }
    }
}

// ================= flash attention (fp16 single-term QK and PV) =================
#define FA_ROWF 144
#define FA_TILE (128*FA_ROWF)
#define FA_STAGE (2*FA_TILE)
#define FA_NSTG 3
#define FA_SMEM (FA_NSTG*FA_STAGE)

__global__ __launch_bounds__(256, 1) void flash_attn(const float* __restrict__ mask)
{
    extern __shared__ char sm[];
    uint32_t sb = smem_u32(sm);
    int tid = threadIdx.x, lane = tid & 31, w = tid >> 5;
    int qt = blockIdx.x, bh = blockIdx.y;
    int b = bh >> 4, h = bh & 15;
    size_t head = (size_t)bh * SS * HDIM;

    #pragma unroll
    for (int j = 0; j < 4; j++) {
        int ch = tid + 256 * j;
        int row = (ch >> 3) & 127, c = ch & 7;
        cp16(sb + row * FA_ROWF + c * 16,
             g_q + head + (size_t)(qt * 128 + row) * HDIM + c * 8);
    }
    CP_COMMIT(); CP_WAIT0();
    __syncthreads();

    uint32_t qf[4][4];
    {
        int ar = lane & 15, ac = (lane >> 4) * 8;
        #pragma unroll
        for (int kb = 0; kb < 4; kb++)
            ldsm_x4(qf[kb], sb + (w * 16 + ar) * FA_ROWF + (kb * 16 + ac) * 2);
    }
    __syncthreads();

    auto load_kv = [&](int s, int kt) {
        uint32_t base = sb + s * FA_STAGE;
        size_t goff = head + (size_t)(kt * 128) * HDIM;
        #pragma unroll
        for (int j = 0; j < 8; j++) {
            int ch = tid + 256 * j;
            int tile = ch >> 10, row = (ch >> 3) & 127, c = ch & 7;
            const __half* sp = (tile == 0) ? g_k : g_v;
            cp16(base + tile * FA_TILE + row * FA_ROWF + c * 16,
                 sp + goff + (size_t)row * HDIM + c * 8);
        }
    };
    load_kv(0, 0); CP_COMMIT();
    load_kv(1, 1); CP_COMMIT();

    int g = lane >> 2, t = lane & 3;
    int krow = (lane & 7) + ((lane >> 4) & 1) * 8, kcol = ((lane >> 3) & 1) * 8;
    int vrow = (lane & 7) + ((lane >> 3) & 1) * 8, vcol = ((lane >> 4) & 1) * 8;
    int qrow0 = qt * 128 + w * 16 + g;
    const float* mrow0 = mask + ((size_t)(b * SS + qrow0)) * SS;

    float m0v = -1e30f, m1v = -1e30f, l0v = 0.f, l1v = 0.f;
    float o[8][4];
    #pragma unroll
    for (int nf = 0; nf < 8; nf++)
        #pragma unroll
        for (int e = 0; e < 4; e++) o[nf][e] = 0.f;

    const int T = 8;
    for (int kt = 0; kt < T; kt++) {
        if (kt < T - 1) { CP_WAIT1(); } else { CP_WAIT0(); }
        __syncthreads();
        if (kt + 2 < T) { load_kv((kt + 2) % FA_NSTG, kt + 2); CP_COMMIT(); }
        uint32_t base = sb + (kt % FA_NSTG) * FA_STAGE;

        float s[16][4];
        #pragma unroll
        for (int np = 0; np < 8; np++) {
            #pragma unroll
            for (int e = 0; e < 4; e++) { s[2*np][e] = 0.f; s[2*np+1][e] = 0.f; }
            #pragma unroll
            for (int kb = 0; kb < 4; kb++) {
                uint32_t ka = base + (np * 16 + krow) * FA_ROWF + (kb * 16 + kcol) * 2;
                uint32_t k4[4];
                ldsm_x4(k4, ka);
                mma16816b(s[2*np],   qf[kb], k4[0], k4[1]);
                mma16816b(s[2*np+1], qf[kb], k4[2], k4[3]);
            }
        }

        float mx0 = -1e30f, mx1 = -1e30f;
        #pragma unroll
        for (int ni = 0; ni < 16; ni++) {
            const float* mp = mrow0 + kt * 128 + ni * 8 + 2 * t;
            float2 mk0 = *(const float2*)mp;
            float2 mk1 = *(const float2*)(mp + 8 * SS);
            s[ni][0] += mk0.x; s[ni][1] += mk0.y;
            s[ni][2] += mk1.x; s[ni][3] += mk1.y;
            mx0 = fmaxf(mx0, fmaxf(s[ni][0], s[ni][1]));
            mx1 = fmaxf(mx1, fmaxf(s[ni][2], s[ni][3]));
        }
        mx0 = fmaxf(mx0, __shfl_xor_sync(0xffffffffu, mx0, 1));
        mx0 = fmaxf(mx0, __shfl_xor_sync(0xffffffffu, mx0, 2));
        mx1 = fmaxf(mx1, __shfl_xor_sync(0xffffffffu, mx1, 1));
        mx1 = fmaxf(mx1, __shfl_xor_sync(0xffffffffu, mx1, 2));
        float mn0 = fmaxf(m0v, mx0), mn1 = fmaxf(m1v, mx1);
        float a0 = __expf(m0v - mn0), a1 = __expf(m1v - mn1);
        m0v = mn0; m1v = mn1;
        l0v *= a0; l1v *= a1;
        #pragma unroll
        for (int nf = 0; nf < 8; nf++) {
            o[nf][0] *= a0; o[nf][1] *= a0; o[nf][2] *= a1; o[nf][3] *= a1;
        }
        #pragma unroll
        for (int ni = 0; ni < 16; ni++) {
            s[ni][0] = __expf(s[ni][0] - mn0); s[ni][1] = __expf(s[ni][1] - mn0);
            s[ni][2] = __expf(s[ni][2] - mn1); s[ni][3] = __expf(s[ni][3] - mn1);
            l0v += s[ni][0] + s[ni][1];
            l1v += s[ni][2] + s[ni][3];
        }

        #pragma unroll
        for (int ks = 0; ks < 8; ks++) {
            uint32_t pa[4];
            pa[0] = pack2h(s[2*ks][0],   s[2*ks][1]);
            pa[1] = pack2h(s[2*ks][2],   s[2*ks][3]);
            pa[2] = pack2h(s[2*ks+1][0], s[2*ks+1][1]);
            pa[3] = pack2h(s[2*ks+1][2], s[2*ks+1][3]);
            #pragma unroll
            for (int nv = 0; nv < 4; nv++) {
                uint32_t va = base + FA_TILE + (ks * 16 + vrow) * FA_ROWF
                              + (nv * 16 + vcol) * 2;
                uint32_t v4[4];
                ldsm_x4_t(v4, va);
                mma16816b(o[2*nv],   pa, v4[0], v4[1]);
                mma16816b(o[2*nv+1], pa, v4[2], v4[3]);
            }
        }
    }

    l0v += __shfl_xor_sync(0xffffffffu, l0v, 1);
    l0v += __shfl_xor_sync(0xffffffffu, l0v, 2);
    l1v += __shfl_xor_sync(0xffffffffu, l1v, 1);
    l1v += __shfl_xor_sync(0xffffffffu, l1v, 2);
    float inv0 = 1.f / l0v, inv1 = 1.f / l1v;
    size_t orow0 = (size_t)(b * SS + qrow0) * DD + h * HDIM;
    size_t orow1 = orow0 + (size_t)8 * DD;
    #pragma unroll
    for (int nf = 0; nf < 8; nf++) {
        int col = nf * 8 + 2 * t;
        store_h2(g_vo, orow0 + col, o[nf][0] * inv0, o[nf][1] * inv0);
        store_h2(g_vo, orow1 + col, o[nf][2] * inv1, o[nf][3] * inv1);
    }
}

// ================= weight transpose (fp16 single) =================
__global__ __launch_bounds__(256) void wsplit_t(const float* __restrict__ W,
                                                __half* __restrict__ hi,
                                                int Kdim, int Ndim) {
    __shared__ float t[32][33];
    size_t loff = (size_t)blockIdx.z * Kdim * Ndim;
    const float* Wl = W + loff;
    __half* hil = hi + loff;
    int k0 = blockIdx.y * 32, n0 = blockIdx.x * 32;
    int tx = threadIdx.x, ty = threadIdx.y;
    #pragma unroll
    for (int i = 0; i < 32; i += 8)
        t[ty + i][tx] = Wl[(size_t)(k0 + ty + i) * Ndim + n0 + tx];
    __syncthreads();
    #pragma unroll
    for (int i = 0; i < 32; i += 8) {
        int n = n0 + ty + i, k = k0 + tx;
        hil[(size_t)n * Kdim + k] = __float2half_rn(t[tx][ty + i]);
    }
}

// ================= embed + PE =================
__global__ __launch_bounds__(256) void embed_kernel(const int* __restrict__ tokens,
                                                    const float* __restrict__ emb,
                                                    float* __restrict__ x,
                                                    __half* __restrict__ xh) {
    int row = blockIdx.x;
    int s = row & (SS - 1);
    int tok = tokens[row];
    const float* e = emb + (size_t)tok * DD;
    int d0 = threadIdx.x * 4;
    float v[4];
    #pragma unroll
    for (int j = 0; j < 4; j++) {
        int d = d0 + j;
        int i2 = d & ~1;
        float denom = powf(10000.0f, (float)i2 / (float)DD);
        float ang = (float)s / denom;
        float pe = (d & 1) ? cosf(ang) : sinf(ang);
        v[j] = e[d] + pe;
    }
    size_t base = (size_t)row * DD + d0;
    *(float4*)(x + base) = make_float4(v[0], v[1], v[2], v[3]);
    store_h2(xh, base, v[0], v[1]);
    store_h2(xh, base + 2, v[2], v[3]);
}

// ================= residual + LayerNorm =================
__device__ __forceinline__ float warpReduceSum(float v) {
    #pragma unroll
    for (int o = 16; o; o >>= 1) v += __shfl_xor_sync(0xffffffffu, v, o);
    return v;
}
__device__ __forceinline__ float blockReduceSum(float v, float* sh) {
    v = warpReduceSum(v);
    int w = threadIdx.x >> 5;
    __syncthreads();
    if ((threadIdx.x & 31) == 0) sh[w] = v;
    __syncthreads();
    if (threadIdx.x < 32) {
        float t = (threadIdx.x < 8) ? sh[threadIdx.x] : 0.f;
        t = warpReduceSum(t);
        if (threadIdx.x == 0) sh[0] = t;
    }
    __syncthreads();
    return sh[0];
}

__global__ __launch_bounds__(256) void ln_kernel(const float* __restrict__ x,
                                                 const float* __restrict__ y,
                                                 const float* __restrict__ gamma,
                                                 const float* __restrict__ beta,
                                                 float* __restrict__ out,
                                                 __half* __restrict__ oh) {
    __shared__ float sh[8];
    size_t row = blockIdx.x;
    int d0 = threadIdx.x * 4;
    float4 a = *(const float4*)(x + row * DD + d0);
    float4 b4 = *(const float4*)(y + row * DD + d0);
    float z[4] = { a.x + b4.x, a.y + b4.y, a.z + b4.z, a.w + b4.w };
    float ssum = z[0] + z[1] + z[2] + z[3];
    ssum = blockReduceSum(ssum, sh);
    float mean = ssum * (1.0f / DD);
    float d2 = 0.f;
    #pragma unroll
    for (int e = 0; e < 4; e++) { float u = z[e] - mean; d2 += u * u; }
    d2 = blockReduceSum(d2, sh);
    float inv = rsqrtf(d2 * (1.0f / DD) + EPSV);
    float4 g4 = *(const float4*)(gamma + d0);
    float4 be4 = *(const float4*)(beta + d0);
    float o0 = g4.x * ((z[0] - mean) * inv) + be4.x;
    float o1 = g4.y * ((z[1] - mean) * inv) + be4.y;
    float o2 = g4.z * ((z[2] - mean) * inv) + be4.z;
    float o3 = g4.w * ((z[3] - mean) * inv) + be4.w;
    size_t base = row * DD + d0;
    *(float4*)(out + base) = make_float4(o0, o1, o2, o3);
    store_h2(oh, base, o0, o1);
    store_h2(oh, base + 2, o2, o3);
}

// ================= orchestration =================
extern "C" void kernel_launch(void* const* d_in, const int* in_sizes, int n_in,
                              void* d_out, int out_size) {
    const int*   tokens = (const int*)d_in[0];
    const float* mask   = (const float*)d_in[1];
    const float* emb    = (const float*)d_in[2];
    const float* qkv_w  = (const float*)d_in[3];
    const float* qkv_b  = (const float*)d_in[4];
    const float* out_w  = (const float*)d_in[5];
    const float* out_b  = (const float*)d_in[6];
    const float* w1     = (const float*)d_in[7];
    const float* b1     = (const float*)d_in[8];
    const float* w2     = (const float*)d_in[9];
    const float* b2     = (const float*)d_in[10];
    const float* gamma  = (const float*)d_in[11];
    const float* beta   = (const float*)d_in[12];
    float* out = (float*)d_out;

    float *px, *py;
    cudaGetSymbolAddress((void**)&px, g_x);
    cudaGetSymbolAddress((void**)&py, g_y);
    __half *pa, *pffa, *pvo, *pwq, *pwo, *pw1, *pw2;
    cudaGetSymbolAddress((void**)&pa,   g_a);
    cudaGetSymbolAddress((void**)&pffa, g_ffa);
    cudaGetSymbolAddress((void**)&pvo,  g_vo);
    cudaGetSymbolAddress((void**)&pwq,  g_wqkv);
    cudaGetSymbolAddress((void**)&pwo,  g_wout);
    cudaGetSymbolAddress((void**)&pw1,  g_w1);
    cudaGetSymbolAddress((void**)&pw2,  g_w2);

    cudaFuncSetAttribute(gemm_mma<0>, cudaFuncAttributeMaxDynamicSharedMemorySize, GT_SMEM);
    cudaFuncSetAttribute(gemm_mma<1>, cudaFuncAttributeMaxDynamicSharedMemorySize, GT_SMEM);
    cudaFuncSetAttribute(gemm_mma<2>, cudaFuncAttributeMaxDynamicSharedMemorySize, GT_SMEM);
    cudaFuncSetAttribute(flash_attn, cudaFuncAttributeMaxDynamicSharedMemorySize, FA_SMEM);

    wsplit_t<<<dim3(3 * DD / 32, DD / 32, LL), dim3(32, 8)>>>(qkv_w, pwq, DD, 3 * DD);
    wsplit_t<<<dim3(DD / 32, DD / 32, LL),     dim3(32, 8)>>>(out_w, pwo, DD, DD);
    wsplit_t<<<dim3(FF / 32, DD / 32, LL),     dim3(32, 8)>>>(w1, pw1, DD, FF);
    wsplit_t<<<dim3(DD / 32, FF / 32, LL),     dim3(32, 8)>>>(w2, pw2, FF, DD);

    embed_kernel<<<MM, 256>>>(tokens, emb, px, pa);

    for (int i = 0; i < LL; i++) {
        size_t l = (size_t)i;
        gemm_mma<2><<<dim3(3 * DD / GBN, MM / GBM), 256, GT_SMEM>>>(
            pa, pwq + l * 3 * DD * DD, qkv_b + l * 3 * DD, nullptr, nullptr, 3 * DD, DD);
        flash_attn<<<dim3(SS / 128, BB * HH), 256, FA_SMEM>>>(mask);
        gemm_mma<0><<<dim3(DD / GBN, MM / GBM), 256, GT_SMEM>>>(
            pvo, pwo + l * DD * DD, out_b + l * DD, py, nullptr, DD, DD);
        ln_kernel<<<MM, 256>>>(px, py, gamma + l * DD, beta + l * DD, px, pa);
        gemm_mma<1><<<dim3(FF / GBN, MM / GBM), 256, GT_SMEM>>>(
            pa, pw1 + l * DD * FF, b1 + l * FF, nullptr, pffa, FF, DD);
        gemm_mma<0><<<dim3(DD / GBN, MM / GBM), 256, GT_SMEM>>>(
            pffa, pw2 + l * FF * DD, b2 + l * DD, py, nullptr, DD, FF);
        ln_kernel<<<MM, 256>>>(px, py, gamma + l * DD, beta + l * DD,
                               (i == LL - 1) ? out : px, pa);
    }
}